// round 11
// baseline (speedup 1.0000x reference)
#include <cuda_runtime.h>
#include <cuda_fp16.h>
#include <math.h>
#include <stdint.h>

#define TT 4096
#define BB 4
#define DD 1024
#define NTOK (TT*BB)
#define CTOK 512
#define NCHUNK 32

// -------- scratch (fp16 intermediates) --------
__device__ __align__(128) __half g_xh[(size_t)NTOK*DD];
__device__ __align__(128) __half g_Wh[(size_t)3*DD*DD];
__device__ __align__(128) __half g_Q [(size_t)NTOK*DD];
__device__ __align__(128) __half g_K [(size_t)NTOK*DD];
__device__ __align__(128) __half g_V [(size_t)NTOK*DD];
__device__ __align__(128) __half g_Kt[(size_t)DD*NTOK];
__device__ __align__(128) __half g_Vt[(size_t)DD*NTOK];
__device__ __align__(128) __half g_S [(size_t)NCHUNK*DD*DD];
__device__ __align__(128) __half g_P [(size_t)NCHUNK*CTOK*CTOK];
__device__ float g_Zc[(size_t)NCHUNK*BB*DD];
__device__ float g_Kc[(size_t)NTOK*DD];
__device__ float g_Dn[NTOK];

#define RSB   80                 // smem row stride bytes (32 halves + pad)
#define ATILE 10240              // 128 rows * 80B
#define BTILE 20480              // 256 rows * 80B
#define STAGE (ATILE + BTILE)    // 30720
#define NSTG  4
#define SMEMSZ (NSTG*STAGE)      // 122880

__device__ __forceinline__ uint32_t smem_u32(const void* p){
    uint32_t a; asm("{ .reg .u64 t; cvta.to.shared.u64 t, %1; cvt.u32.u64 %0, t; }":"=r"(a):"l"(p)); return a;
}
__device__ __forceinline__ void cp16(uint32_t s, const void* g){
    asm volatile("cp.async.cg.shared.global [%0], [%1], 16;" :: "r"(s), "l"(g));
}

// =====================================================================
// fp16 mma.sync NT GEMM: C[M,N] = A[M,K] * B[N,K]^T  (both K-major fp16)
// BM=128, BN=256, BK=32, 4-stage cp.async. 256 thr, 8 warps (2m x 4n),
// warp tile 64x64, m16n8k16 fp32-acc.  (proven R8 core, WT removed)
// =====================================================================
template<bool OUTF32, int ACT, bool MASK, bool BETA1, bool DIVEPI>
__global__ void __launch_bounds__(256, 1) hgemm(
    const __half* __restrict__ A, const __half* __restrict__ B,
    void* __restrict__ Cv, const float* __restrict__ denom,
    int K, int lda, int ldb, int ldc,
    long sA, long sB, long sC)
{
    extern __shared__ char smem[];
    const uint32_t sbase = smem_u32(smem);
    const int tid  = threadIdx.x;
    const int lane = tid & 31;
    const int warp = tid >> 5;
    const int wm = warp >> 2, wn = warp & 3;
    const int gid = lane >> 2, tig = lane & 3;
    const int bz = blockIdx.z;
    const int row0 = blockIdx.y * 128;
    const int col0 = blockIdx.x * 256;

    const __half* Ah = A + (long)bz*sA;
    const __half* Bh = B + (long)bz*sB;
    float*  Cf  = (float*)Cv + (long)bz*sC;
    __half* Chh = (__half*)Cv + (long)bz*sC;

    float acc[4][8][4] = {};

    // fragment ldmatrix lane offsets (bytes, within stage)
    const uint32_t a_lm = (uint32_t)(wm*64*RSB + (lane&15)*RSB + (lane>>4)*16);
    const uint32_t b_lm = (uint32_t)(ATILE + wn*64*RSB
                        + ((lane&7) + ((lane>>4)&1)*8)*RSB + ((lane>>3)&1)*16);

    // cp.async staging: A 512 chunks (2/thr), B 1024 chunks (4/thr)
    const int a0 = tid*2, a1 = tid*2 + 1;
    const __half* acp0 = Ah + (long)(row0 + (a0>>2))*lda + (a0&3)*8;
    const __half* acp1 = Ah + (long)(row0 + (a1>>2))*lda + (a1&3)*8;
    const uint32_t acs0 = sbase + (a0>>2)*RSB + (a0&3)*16;
    const uint32_t acs1 = sbase + (a1>>2)*RSB + (a1&3)*16;
    const int b0 = tid*4;
    const __half* bcp0 = Bh + (long)(col0 + ((b0  )>>2))*ldb + ((b0  )&3)*8;
    const __half* bcp1 = Bh + (long)(col0 + ((b0+1)>>2))*ldb + ((b0+1)&3)*8;
    const __half* bcp2 = Bh + (long)(col0 + ((b0+2)>>2))*ldb + ((b0+2)&3)*8;
    const __half* bcp3 = Bh + (long)(col0 + ((b0+3)>>2))*ldb + ((b0+3)&3)*8;
    const uint32_t bcs0 = sbase + ATILE + ((b0  )>>2)*RSB + ((b0  )&3)*16;
    const uint32_t bcs1 = sbase + ATILE + ((b0+1)>>2)*RSB + ((b0+1)&3)*16;
    const uint32_t bcs2 = sbase + ATILE + ((b0+2)>>2)*RSB + ((b0+2)&3)*16;
    const uint32_t bcs3 = sbase + ATILE + ((b0+3)>>2)*RSB + ((b0+3)&3)*16;

    auto loadcp = [&](int st, int k0){
        uint32_t so = st*STAGE;
        cp16(acs0 + so, acp0 + k0);
        cp16(acs1 + so, acp1 + k0);
        cp16(bcs0 + so, bcp0 + k0);
        cp16(bcs1 + so, bcp1 + k0);
        cp16(bcs2 + so, bcp2 + k0);
        cp16(bcs3 + so, bcp3 + k0);
        asm volatile("cp.async.commit_group;" ::: "memory");
    };

    auto mma_stage = [&](int st){
        uint32_t base = sbase + st*STAGE;
        #pragma unroll
        for (int kk = 0; kk < 2; kk++){
            uint32_t af[4][4], bf[8][2];
            #pragma unroll
            for (int mt = 0; mt < 4; mt++){
                uint32_t ad = base + a_lm + mt*(16*RSB) + kk*32;
                asm volatile("ldmatrix.sync.aligned.m8n8.x4.shared.b16 {%0,%1,%2,%3},[%4];"
                    : "=r"(af[mt][0]),"=r"(af[mt][1]),"=r"(af[mt][2]),"=r"(af[mt][3])
                    : "r"(ad));
            }
            #pragma unroll
            for (int p = 0; p < 4; p++){
                uint32_t bd = base + b_lm + p*(16*RSB) + kk*32;
                uint32_t r0,r1,r2,r3;
                asm volatile("ldmatrix.sync.aligned.m8n8.x4.shared.b16 {%0,%1,%2,%3},[%4];"
                    : "=r"(r0),"=r"(r1),"=r"(r2),"=r"(r3) : "r"(bd));
                bf[2*p][0]=r0; bf[2*p][1]=r1; bf[2*p+1][0]=r2; bf[2*p+1][1]=r3;
            }
            #pragma unroll
            for (int mt = 0; mt < 4; mt++)
                #pragma unroll
                for (int nt = 0; nt < 8; nt++)
                    asm volatile(
                        "mma.sync.aligned.m16n8k16.row.col.f32.f16.f16.f32 "
                        "{%0,%1,%2,%3},{%4,%5,%6,%7},{%8,%9},{%0,%1,%2,%3};"
                        : "+f"(acc[mt][nt][0]),"+f"(acc[mt][nt][1]),
                          "+f"(acc[mt][nt][2]),"+f"(acc[mt][nt][3])
                        : "r"(af[mt][0]),"r"(af[mt][1]),"r"(af[mt][2]),"r"(af[mt][3]),
                          "r"(bf[nt][0]),"r"(bf[nt][1]));
        }
    };

    const int n = K >> 5;
    loadcp(0, 0);
    loadcp(1, 32);
    loadcp(2, 64);
    for (int s = 0; s < n; s++){
        if (s < n-2)       asm volatile("cp.async.wait_group 2;" ::: "memory");
        else if (s == n-2) asm volatile("cp.async.wait_group 1;" ::: "memory");
        else               asm volatile("cp.async.wait_group 0;" ::: "memory");
        __syncthreads();
        if (s + 3 < n) loadcp((s+3)&3, (s+3)*32);
        mma_stage(s & 3);
    }

    // ---- epilogue ----
    #pragma unroll
    for (int mt = 0; mt < 4; mt++){
        int r0 = row0 + wm*64 + mt*16 + gid;
        int r1 = r0 + 8;
        float dn0 = 1.0f, dn1 = 1.0f;
        if (DIVEPI){ dn0 = denom[(long)bz*CTOK + r0]; dn1 = denom[(long)bz*CTOK + r1]; }
        #pragma unroll
        for (int nt = 0; nt < 8; nt++){
            int c0 = col0 + wn*64 + nt*8 + 2*tig;
            float v[4];
            #pragma unroll
            for (int e = 0; e < 4; e++){
                float f = acc[mt][nt][e];
                if (ACT == 1) f = (f > 0.0f) ? (f + 1.0f) : expf(f);
                if (MASK){
                    int r = (e < 2) ? r0 : r1;
                    int c = c0 + (e & 1);
                    if ((c >> 2) > (r >> 2)) f = 0.0f;
                }
                v[e] = f;
            }
            if (OUTF32){
                long o0 = (long)r0*ldc + c0, o1 = (long)r1*ldc + c0;
                float2 p0 = make_float2(v[0], v[1]);
                float2 p1 = make_float2(v[2], v[3]);
                if (BETA1){
                    float2 q0 = *(float2*)(Cf+o0), q1 = *(float2*)(Cf+o1);
                    p0.x += q0.x; p0.y += q0.y; p1.x += q1.x; p1.y += q1.y;
                }
                if (DIVEPI){ p0.x /= dn0; p0.y /= dn0; p1.x /= dn1; p1.y /= dn1; }
                *(float2*)(Cf+o0) = p0;
                *(float2*)(Cf+o1) = p1;
            } else {
                *(__half2*)(Chh + (long)r0*ldc + c0) = __floats2half2_rn(v[0], v[1]);
                *(__half2*)(Chh + (long)r1*ldc + c0) = __floats2half2_rn(v[2], v[3]);
            }
        }
    }
}

// -------- tiled fp16 transpose: dst[c][r] = src[r][c] --------
// src[rows][cols], dst[cols][rows]; rows,cols % 64 == 0. 256 threads.
__global__ void transpose_kernel(const __half* __restrict__ src,
                                 __half* __restrict__ dst,
                                 int rows, int cols)
{
    __shared__ __half tile[64][72];
    int r0 = blockIdx.x * 64;
    int c0 = blockIdx.y * 64;
    int tid = threadIdx.x;
    #pragma unroll
    for (int it = 0; it < 2; it++){
        int task = it*256 + tid;          // 0..511
        int r = task >> 3, ch = task & 7; // 64 rows x 8 chunks of 8 halves
        uint4 v = *(const uint4*)&src[(long)(r0+r)*cols + c0 + ch*8];
        *(uint4*)&tile[r][ch*8] = v;
    }
    __syncthreads();
    #pragma unroll
    for (int it = 0; it < 2; it++){
        int task = it*256 + tid;
        int d = task >> 3, ch = task & 7; // 64 out-rows x 8 chunks of 8 halves
        __half tmp[8];
        #pragma unroll
        for (int i = 0; i < 8; i++) tmp[i] = tile[ch*8+i][d];
        *(uint4*)&dst[(long)(c0+d)*rows + r0 + ch*8] = *(uint4*)tmp;
    }
}

// -------- fp32 -> fp16 conversion (vectorized) --------
__global__ void f2h_kernel(const float* __restrict__ in, __half* __restrict__ out, int n8)
{
    int i = blockIdx.x * blockDim.x + threadIdx.x;
    if (i >= n8) return;
    float4 a = ((const float4*)in)[2*i];
    float4 b = ((const float4*)in)[2*i+1];
    __half2 h[4] = { __floats2half2_rn(a.x,a.y), __floats2half2_rn(a.z,a.w),
                     __floats2half2_rn(b.x,b.y), __floats2half2_rn(b.z,b.w) };
    ((uint4*)out)[i] = *(uint4*)h;
}

// -------- aux kernels --------
__global__ void prefix_kernel(__half* __restrict__ S)
{
    long e = (long)blockIdx.x * blockDim.x + threadIdx.x;
    float acc = 0.0f;
    for (int c = 0; c < NCHUNK; c++){
        long off = (long)c * DD * DD + e;
        float v = __half2float(S[off]);
        S[off] = __float2half(acc);
        acc += v;
    }
}
__global__ void kchunksum_kernel(const __half* __restrict__ Kp, float* __restrict__ Zc)
{
    int id = blockIdx.x * blockDim.x + threadIdx.x;   // < NCHUNK*4096
    int c = id >> 12, bd = id & 4095;
    const __half* p = Kp + (long)c*128*4096 + bd;
    float s = 0.0f;
    #pragma unroll 8
    for (int t = 0; t < 128; t++) s += __half2float(p[(long)t*4096]);
    Zc[id] = s;
}
__global__ void kcum2_kernel(const __half* __restrict__ Kp,
                             const float* __restrict__ Zc,
                             float* __restrict__ Kc)
{
    int id = blockIdx.x * blockDim.x + threadIdx.x;   // < NCHUNK*4096
    int c = id >> 12, bd = id & 4095;
    float acc = 0.0f;
    for (int cp = 0; cp < c; cp++) acc += Zc[cp*4096 + bd];
    const __half* p = Kp + (long)c*128*4096 + bd;
    float*       o = Kc + (long)c*128*4096 + bd;
    #pragma unroll 4
    for (int t = 0; t < 128; t++){
        acc += __half2float(p[(long)t*4096]);
        o[(long)t*4096] = acc;
    }
}
__global__ void denom_kernel(const __half* __restrict__ Qp,
                             const float* __restrict__ Kc,
                             float* __restrict__ dn)
{
    int warp = (blockIdx.x * blockDim.x + threadIdx.x) >> 5;
    int lane = threadIdx.x & 31;
    if (warp >= NTOK) return;
    const __half* qv = Qp + (long)warp * DD;
    const float*  zv = Kc + (long)warp * DD;
    float s = 0.0f;
    for (int d = lane; d < DD; d += 32) s += __half2float(qv[d]) * zv[d];
    #pragma unroll
    for (int o = 16; o; o >>= 1) s += __shfl_down_sync(0xffffffffu, s, o);
    if (lane == 0) dn[warp] = s;
}

extern "C" void kernel_launch(void* const* d_in, const int* in_sizes, int n_in,
                              void* d_out, int out_size)
{
    const float* x  = (const float*)d_in[0];
    const float* Wq = (const float*)d_in[1];
    const float* Wk = (const float*)d_in[2];
    const float* Wv = (const float*)d_in[3];
    float* out = (float*)d_out;

    __half *xh,*Wh,*Qh,*Kh,*Vh,*Kth,*Vth,*Sh,*Ph; float *Zc,*Kc,*Dn;
    cudaGetSymbolAddress((void**)&xh,  g_xh);
    cudaGetSymbolAddress((void**)&Wh,  g_Wh);
    cudaGetSymbolAddress((void**)&Qh,  g_Q);
    cudaGetSymbolAddress((void**)&Kh,  g_K);
    cudaGetSymbolAddress((void**)&Vh,  g_V);
    cudaGetSymbolAddress((void**)&Kth, g_Kt);
    cudaGetSymbolAddress((void**)&Vth, g_Vt);
    cudaGetSymbolAddress((void**)&Sh,  g_S);
    cudaGetSymbolAddress((void**)&Ph,  g_P);
    cudaGetSymbolAddress((void**)&Zc,  g_Zc);
    cudaGetSymbolAddress((void**)&Kc,  g_Kc);
    cudaGetSymbolAddress((void**)&Dn,  g_Dn);
    __half *Wqh = Wh, *Wkh = Wh + (size_t)DD*DD, *Wvh = Wh + (size_t)2*DD*DD;

    cudaFuncSetAttribute(hgemm<false,1,false,false,false>, cudaFuncAttributeMaxDynamicSharedMemorySize, SMEMSZ);
    cudaFuncSetAttribute(hgemm<false,0,false,false,false>, cudaFuncAttributeMaxDynamicSharedMemorySize, SMEMSZ);
    cudaFuncSetAttribute(hgemm<true ,0,false,false,false>, cudaFuncAttributeMaxDynamicSharedMemorySize, SMEMSZ);
    cudaFuncSetAttribute(hgemm<false,0,true ,false,false>, cudaFuncAttributeMaxDynamicSharedMemorySize, SMEMSZ);
    cudaFuncSetAttribute(hgemm<true ,0,false,true ,true >, cudaFuncAttributeMaxDynamicSharedMemorySize, SMEMSZ);

    // 0) convert inputs to fp16
    f2h_kernel<<<((size_t)NTOK*DD/8 + 255)/256, 256>>>(x,  xh,  NTOK*DD/8);
    f2h_kernel<<<(DD*DD/8 + 255)/256, 256>>>(Wq, Wqh, DD*DD/8);
    f2h_kernel<<<(DD*DD/8 + 255)/256, 256>>>(Wk, Wkh, DD*DD/8);
    f2h_kernel<<<(DD*DD/8 + 255)/256, 256>>>(Wv, Wvh, DD*DD/8);

    // 1) Q = elu1(x Wq^T)
    hgemm<false,1,false,false,false><<<dim3(4,128,1),256,SMEMSZ>>>(
        xh, Wqh, Qh, nullptr, DD, DD, DD, DD, 0, 0, 0);
    // 2) K = elu1(x Wk^T)   (row-major, coalesced)
    hgemm<false,1,false,false,false><<<dim3(4,128,1),256,SMEMSZ>>>(
        xh, Wkh, Kh, nullptr, DD, DD, DD, DD, 0, 0, 0);
    // 3) V = x Wv^T         (row-major, coalesced)
    hgemm<false,0,false,false,false><<<dim3(4,128,1),256,SMEMSZ>>>(
        xh, Wvh, Vh, nullptr, DD, DD, DD, DD, 0, 0, 0);
    // 3b) transposed copies Kt[D,NTOK], Vt[D,NTOK] (tiled, coalesced both sides)
    transpose_kernel<<<dim3(NTOK/64, DD/64), 256>>>(Kh, Kth, NTOK, DD);
    transpose_kernel<<<dim3(NTOK/64, DD/64), 256>>>(Vh, Vth, NTOK, DD);
    // 4) St_c[dm,dk] = Vt_c · Kt_c^T
    hgemm<false,0,false,false,false><<<dim3(4,8,NCHUNK),256,SMEMSZ>>>(
        Vth, Kth, Sh, nullptr, CTOK, NTOK, NTOK, DD,
        (long)CTOK, (long)CTOK, (long)DD*DD);
    // 5) exclusive prefix over chunks
    prefix_kernel<<<DD*DD/256, 256>>>(Sh);
    // 6) denominator path (parallel 2-pass cumsum, then dot)
    kchunksum_kernel<<<NCHUNK*BB*DD/256, 256>>>(Kh, Zc);
    kcum2_kernel<<<NCHUNK*BB*DD/256, 256>>>(Kh, Zc, Kc);
    denom_kernel<<<NTOK/8, 256>>>(Qh, Kc, Dn);
    // 7) Y1 = Q_c · Sprefix_c^T   (fp32 out)
    hgemm<true,0,false,false,false><<<dim3(4,4,NCHUNK),256,SMEMSZ>>>(
        Qh, Sh, out, nullptr, DD, DD, DD, DD,
        (long)CTOK*DD, (long)DD*DD, (long)CTOK*DD);
    // 8) P = mask(Q_c · K_c^T)
    hgemm<false,0,true,false,false><<<dim3(2,4,NCHUNK),256,SMEMSZ>>>(
        Qh, Kh, Ph, nullptr, DD, DD, DD, CTOK,
        (long)CTOK*DD, (long)CTOK*DD, (long)CTOK*CTOK);
    // 9) Y += P_c · Vt_c^T, then / denom  (fp32 out)
    hgemm<true,0,false,true,true><<<dim3(4,4,NCHUNK),256,SMEMSZ>>>(
        Ph, Vth, out, Dn, CTOK, CTOK, NTOK, DD,
        (long)CTOK*CTOK, (long)CTOK, (long)CTOK*DD);
}

// round 12
// speedup vs baseline: 1.0105x; 1.0105x over previous
#include <cuda_runtime.h>
#include <cuda_fp16.h>
#include <math.h>
#include <stdint.h>

#define TT 4096
#define BB 4
#define DD 1024
#define NTOK (TT*BB)
#define CTOK 512
#define NCHUNK 32

// -------- scratch (fp16 intermediates) --------
__device__ __align__(128) __half g_xh[(size_t)NTOK*DD];
__device__ __align__(128) __half g_Wh[(size_t)3*DD*DD];
__device__ __align__(128) __half g_Q [(size_t)NTOK*DD];
__device__ __align__(128) __half g_K [(size_t)NTOK*DD];
__device__ __align__(128) __half g_Kt[(size_t)DD*NTOK];
__device__ __align__(128) __half g_Vt[(size_t)DD*NTOK];
__device__ __align__(128) __half g_S [(size_t)NCHUNK*DD*DD];
__device__ __align__(128) __half g_P [(size_t)NCHUNK*CTOK*CTOK];
__device__ float g_Zc[(size_t)NCHUNK*BB*DD];
__device__ float g_Kc[(size_t)NTOK*DD];
__device__ float g_Dn[NTOK];

#define RSB   80                 // smem row stride bytes (32 halves + pad)
#define ATILE 10240              // 128 rows * 80B
#define BTILE 20480              // 256 rows * 80B
#define STAGE (ATILE + BTILE)    // 30720
#define NSTG  4
#define SMEMSZ (NSTG*STAGE)      // 122880

__device__ __forceinline__ uint32_t smem_u32(const void* p){
    uint32_t a; asm("{ .reg .u64 t; cvta.to.shared.u64 t, %1; cvt.u32.u64 %0, t; }":"=r"(a):"l"(p)); return a;
}
__device__ __forceinline__ void cp16(uint32_t s, const void* g){
    asm volatile("cp.async.cg.shared.global [%0], [%1], 16;" :: "r"(s), "l"(g));
}

// =====================================================================
// fp16 mma.sync NT GEMM: C[M,N] = A[M,K] * B[N,K]^T  (both K-major fp16)
// BM=128, BN=256, BK=32, 4-stage cp.async. 256 thr, 8 warps (2m x 4n),
// warp tile 64x64, m16n8k16 fp32-acc. (R8 core + fragment double-buffer)
// =====================================================================
template<bool OUTF32, int ACT, bool MASK, bool BETA1, bool DIVEPI, bool WN, bool WT>
__global__ void __launch_bounds__(256, 1) hgemm(
    const __half* __restrict__ A, const __half* __restrict__ B,
    void* __restrict__ Cv, __half* __restrict__ Ct,
    const float* __restrict__ denom,
    int K, int lda, int ldb, int ldc, int ldt,
    long sA, long sB, long sC, long sCt)
{
    extern __shared__ char smem[];
    const uint32_t sbase = smem_u32(smem);
    const int tid  = threadIdx.x;
    const int lane = tid & 31;
    const int warp = tid >> 5;
    const int wm = warp >> 2, wn = warp & 3;
    const int gid = lane >> 2, tig = lane & 3;
    const int bz = blockIdx.z;
    const int row0 = blockIdx.y * 128;
    const int col0 = blockIdx.x * 256;

    const __half* Ah = A + (long)bz*sA;
    const __half* Bh = B + (long)bz*sB;
    float*  Cf  = (float*)Cv + (long)bz*sC;
    __half* Chh = (__half*)Cv + (long)bz*sC;
    __half* Cth = Ct + (long)bz*sCt;

    // fully-masked tile: write zeros and exit (step-8 lower-triangular skip)
    if (MASK && !OUTF32 && WN && !WT){
        if ((col0 >> 2) > ((row0 + 127) >> 2)){
            #pragma unroll
            for (int it = 0; it < 16; it++){
                int task = it*256 + tid;            // 4096 x 16B = 128x256 halves
                int r = task >> 5, ch = task & 31;
                uint4 z = make_uint4(0,0,0,0);
                *(uint4*)&Chh[(long)(row0 + r)*ldc + col0 + ch*8] = z;
            }
            return;
        }
    }

    float acc[4][8][4] = {};

    // fragment ldmatrix lane offsets (bytes, within stage)
    const uint32_t a_lm = (uint32_t)(wm*64*RSB + (lane&15)*RSB + (lane>>4)*16);
    const uint32_t b_lm = (uint32_t)(ATILE + wn*64*RSB
                        + ((lane&7) + ((lane>>4)&1)*8)*RSB + ((lane>>3)&1)*16);

    // cp.async staging: A 512 chunks (2/thr), B 1024 chunks (4/thr)
    const int a0 = tid*2, a1 = tid*2 + 1;
    const __half* acp0 = Ah + (long)(row0 + (a0>>2))*lda + (a0&3)*8;
    const __half* acp1 = Ah + (long)(row0 + (a1>>2))*lda + (a1&3)*8;
    const uint32_t acs0 = sbase + (a0>>2)*RSB + (a0&3)*16;
    const uint32_t acs1 = sbase + (a1>>2)*RSB + (a1&3)*16;
    const int b0 = tid*4;
    const __half* bcp0 = Bh + (long)(col0 + ((b0  )>>2))*ldb + ((b0  )&3)*8;
    const __half* bcp1 = Bh + (long)(col0 + ((b0+1)>>2))*ldb + ((b0+1)&3)*8;
    const __half* bcp2 = Bh + (long)(col0 + ((b0+2)>>2))*ldb + ((b0+2)&3)*8;
    const __half* bcp3 = Bh + (long)(col0 + ((b0+3)>>2))*ldb + ((b0+3)&3)*8;
    const uint32_t bcs0 = sbase + ATILE + ((b0  )>>2)*RSB + ((b0  )&3)*16;
    const uint32_t bcs1 = sbase + ATILE + ((b0+1)>>2)*RSB + ((b0+1)&3)*16;
    const uint32_t bcs2 = sbase + ATILE + ((b0+2)>>2)*RSB + ((b0+2)&3)*16;
    const uint32_t bcs3 = sbase + ATILE + ((b0+3)>>2)*RSB + ((b0+3)&3)*16;

    auto loadcp = [&](int st, int k0){
        uint32_t so = st*STAGE;
        cp16(acs0 + so, acp0 + k0);
        cp16(acs1 + so, acp1 + k0);
        cp16(bcs0 + so, bcp0 + k0);
        cp16(bcs1 + so, bcp1 + k0);
        cp16(bcs2 + so, bcp2 + k0);
        cp16(bcs3 + so, bcp3 + k0);
        asm volatile("cp.async.commit_group;" ::: "memory");
    };

    auto load_frags = [&](uint32_t base, int kk, uint32_t af[4][4], uint32_t bf[8][2]){
        #pragma unroll
        for (int mt = 0; mt < 4; mt++){
            uint32_t ad = base + a_lm + mt*(16*RSB) + kk*32;
            asm volatile("ldmatrix.sync.aligned.m8n8.x4.shared.b16 {%0,%1,%2,%3},[%4];"
                : "=r"(af[mt][0]),"=r"(af[mt][1]),"=r"(af[mt][2]),"=r"(af[mt][3])
                : "r"(ad));
        }
        #pragma unroll
        for (int p = 0; p < 4; p++){
            uint32_t bd = base + b_lm + p*(16*RSB) + kk*32;
            uint32_t r0,r1,r2,r3;
            asm volatile("ldmatrix.sync.aligned.m8n8.x4.shared.b16 {%0,%1,%2,%3},[%4];"
                : "=r"(r0),"=r"(r1),"=r"(r2),"=r"(r3) : "r"(bd));
            bf[2*p][0]=r0; bf[2*p][1]=r1; bf[2*p+1][0]=r2; bf[2*p+1][1]=r3;
        }
    };

    auto mma_stage = [&](int st){
        uint32_t base = sbase + st*STAGE;
        uint32_t af[2][4][4], bf[2][8][2];
        load_frags(base, 0, af[0], bf[0]);
        #pragma unroll
        for (int kk = 0; kk < 2; kk++){
            if (kk == 0) load_frags(base, 1, af[1], bf[1]);   // hoisted under kk=0 MMAs
            #pragma unroll
            for (int mt = 0; mt < 4; mt++)
                #pragma unroll
                for (int nt = 0; nt < 8; nt++)
                    asm volatile(
                        "mma.sync.aligned.m16n8k16.row.col.f32.f16.f16.f32 "
                        "{%0,%1,%2,%3},{%4,%5,%6,%7},{%8,%9},{%0,%1,%2,%3};"
                        : "+f"(acc[mt][nt][0]),"+f"(acc[mt][nt][1]),
                          "+f"(acc[mt][nt][2]),"+f"(acc[mt][nt][3])
                        : "r"(af[kk][mt][0]),"r"(af[kk][mt][1]),"r"(af[kk][mt][2]),"r"(af[kk][mt][3]),
                          "r"(bf[kk][nt][0]),"r"(bf[kk][nt][1]));
        }
    };

    const int n = K >> 5;
    loadcp(0, 0);
    loadcp(1, 32);
    loadcp(2, 64);
    for (int s = 0; s < n; s++){
        if (s < n-2)       asm volatile("cp.async.wait_group 2;" ::: "memory");
        else if (s == n-2) asm volatile("cp.async.wait_group 1;" ::: "memory");
        else               asm volatile("cp.async.wait_group 0;" ::: "memory");
        __syncthreads();
        if (s + 3 < n) loadcp((s+3)&3, (s+3)*32);
        mma_stage(s & 3);
    }

    // ---- epilogue ----
    #pragma unroll
    for (int mt = 0; mt < 4; mt++){
        int r0 = row0 + wm*64 + mt*16 + gid;
        int r1 = r0 + 8;
        float dn0 = 1.0f, dn1 = 1.0f;
        if (DIVEPI){ dn0 = denom[(long)bz*CTOK + r0]; dn1 = denom[(long)bz*CTOK + r1]; }
        #pragma unroll
        for (int nt = 0; nt < 8; nt++){
            int c0 = col0 + wn*64 + nt*8 + 2*tig;
            float v[4];
            #pragma unroll
            for (int e = 0; e < 4; e++){
                float f = acc[mt][nt][e];
                if (ACT == 1) f = (f > 0.0f) ? (f + 1.0f) : expf(f);
                if (MASK){
                    int r = (e < 2) ? r0 : r1;
                    int c = c0 + (e & 1);
                    if ((c >> 2) > (r >> 2)) f = 0.0f;
                }
                v[e] = f;
            }
            if (WN){
                if (OUTF32){
                    long o0 = (long)r0*ldc + c0, o1 = (long)r1*ldc + c0;
                    float2 p0 = make_float2(v[0], v[1]);
                    float2 p1 = make_float2(v[2], v[3]);
                    if (BETA1){
                        float2 q0 = *(float2*)(Cf+o0), q1 = *(float2*)(Cf+o1);
                        p0.x += q0.x; p0.y += q0.y; p1.x += q1.x; p1.y += q1.y;
                    }
                    if (DIVEPI){ p0.x /= dn0; p0.y /= dn0; p1.x /= dn1; p1.y /= dn1; }
                    *(float2*)(Cf+o0) = p0;
                    *(float2*)(Cf+o1) = p1;
                } else {
                    *(__half2*)(Chh + (long)r0*ldc + c0) = __floats2half2_rn(v[0], v[1]);
                    *(__half2*)(Chh + (long)r1*ldc + c0) = __floats2half2_rn(v[2], v[3]);
                }
            }
            if (WT){
                Cth[(long)(c0  )*ldt + r0] = __float2half(v[0]);
                Cth[(long)(c0+1)*ldt + r0] = __float2half(v[1]);
                Cth[(long)(c0  )*ldt + r1] = __float2half(v[2]);
                Cth[(long)(c0+1)*ldt + r1] = __float2half(v[3]);
            }
        }
    }
}

// -------- fp32 -> fp16 conversion (4x ILP) --------
__global__ void f2h_kernel(const float* __restrict__ in, __half* __restrict__ out, int n8)
{
    int i0 = (blockIdx.x * blockDim.x + threadIdx.x) * 4;
    #pragma unroll
    for (int u = 0; u < 4; u++){
        int i = i0 + u;
        if (i >= n8) break;
        float4 a = ((const float4*)in)[2*i];
        float4 b = ((const float4*)in)[2*i+1];
        __half2 h[4] = { __floats2half2_rn(a.x,a.y), __floats2half2_rn(a.z,a.w),
                         __floats2half2_rn(b.x,b.y), __floats2half2_rn(b.z,b.w) };
        ((uint4*)out)[i] = *(uint4*)h;
    }
}

// -------- aux kernels --------
__global__ void prefix_kernel(__half* __restrict__ S)
{
    long e = (long)blockIdx.x * blockDim.x + threadIdx.x;
    float acc = 0.0f;
    for (int c = 0; c < NCHUNK; c++){
        long off = (long)c * DD * DD + e;
        float v = __half2float(S[off]);
        S[off] = __float2half(acc);
        acc += v;
    }
}
__global__ void kchunksum_kernel(const __half* __restrict__ Kp, float* __restrict__ Zc)
{
    int id = blockIdx.x * blockDim.x + threadIdx.x;   // < NCHUNK*4096
    int c = id >> 12, bd = id & 4095;
    const __half* p = Kp + (long)c*128*4096 + bd;
    float s = 0.0f;
    #pragma unroll 8
    for (int t = 0; t < 128; t++) s += __half2float(p[(long)t*4096]);
    Zc[id] = s;
}
__global__ void kcum2_kernel(const __half* __restrict__ Kp,
                             const float* __restrict__ Zc,
                             float* __restrict__ Kc)
{
    int id = blockIdx.x * blockDim.x + threadIdx.x;   // < NCHUNK*4096
    int c = id >> 12, bd = id & 4095;
    float acc = 0.0f;
    for (int cp = 0; cp < c; cp++) acc += Zc[cp*4096 + bd];
    const __half* p = Kp + (long)c*128*4096 + bd;
    float*       o = Kc + (long)c*128*4096 + bd;
    #pragma unroll 4
    for (int t = 0; t < 128; t++){
        acc += __half2float(p[(long)t*4096]);
        o[(long)t*4096] = acc;
    }
}
__global__ void denom_kernel(const __half* __restrict__ Qp,
                             const float* __restrict__ Kc,
                             float* __restrict__ dn)
{
    int warp = (blockIdx.x * blockDim.x + threadIdx.x) >> 5;
    int lane = threadIdx.x & 31;
    if (warp >= NTOK) return;
    const __half* qv = Qp + (long)warp * DD;
    const float*  zv = Kc + (long)warp * DD;
    float s = 0.0f;
    for (int d = lane; d < DD; d += 32) s += __half2float(qv[d]) * zv[d];
    #pragma unroll
    for (int o = 16; o; o >>= 1) s += __shfl_down_sync(0xffffffffu, s, o);
    if (lane == 0) dn[warp] = s;
}

extern "C" void kernel_launch(void* const* d_in, const int* in_sizes, int n_in,
                              void* d_out, int out_size)
{
    const float* x  = (const float*)d_in[0];
    const float* Wq = (const float*)d_in[1];
    const float* Wk = (const float*)d_in[2];
    const float* Wv = (const float*)d_in[3];
    float* out = (float*)d_out;

    __half *xh,*Wh,*Qh,*Kh,*Kth,*Vth,*Sh,*Ph; float *Zc,*Kc,*Dn;
    cudaGetSymbolAddress((void**)&xh,  g_xh);
    cudaGetSymbolAddress((void**)&Wh,  g_Wh);
    cudaGetSymbolAddress((void**)&Qh,  g_Q);
    cudaGetSymbolAddress((void**)&Kh,  g_K);
    cudaGetSymbolAddress((void**)&Kth, g_Kt);
    cudaGetSymbolAddress((void**)&Vth, g_Vt);
    cudaGetSymbolAddress((void**)&Sh,  g_S);
    cudaGetSymbolAddress((void**)&Ph,  g_P);
    cudaGetSymbolAddress((void**)&Zc,  g_Zc);
    cudaGetSymbolAddress((void**)&Kc,  g_Kc);
    cudaGetSymbolAddress((void**)&Dn,  g_Dn);
    __half *Wqh = Wh, *Wkh = Wh + (size_t)DD*DD, *Wvh = Wh + (size_t)2*DD*DD;

    cudaFuncSetAttribute(hgemm<false,1,false,false,false,true ,false>, cudaFuncAttributeMaxDynamicSharedMemorySize, SMEMSZ);
    cudaFuncSetAttribute(hgemm<false,1,false,false,false,true ,true >, cudaFuncAttributeMaxDynamicSharedMemorySize, SMEMSZ);
    cudaFuncSetAttribute(hgemm<false,0,false,false,false,false,true >, cudaFuncAttributeMaxDynamicSharedMemorySize, SMEMSZ);
    cudaFuncSetAttribute(hgemm<false,0,false,false,false,true ,false>, cudaFuncAttributeMaxDynamicSharedMemorySize, SMEMSZ);
    cudaFuncSetAttribute(hgemm<true ,0,false,false,false,true ,false>, cudaFuncAttributeMaxDynamicSharedMemorySize, SMEMSZ);
    cudaFuncSetAttribute(hgemm<false,0,true ,false,false,true ,false>, cudaFuncAttributeMaxDynamicSharedMemorySize, SMEMSZ);
    cudaFuncSetAttribute(hgemm<true ,0,false,true ,true ,true ,false>, cudaFuncAttributeMaxDynamicSharedMemorySize, SMEMSZ);

    // 0) convert inputs to fp16
    f2h_kernel<<<((size_t)NTOK*DD/8/4 + 255)/256, 256>>>(x,  xh,  NTOK*DD/8);
    f2h_kernel<<<(DD*DD/8/4 + 255)/256, 256>>>(Wq, Wqh, DD*DD/8);
    f2h_kernel<<<(DD*DD/8/4 + 255)/256, 256>>>(Wk, Wkh, DD*DD/8);
    f2h_kernel<<<(DD*DD/8/4 + 255)/256, 256>>>(Wv, Wvh, DD*DD/8);

    // 1) Q = elu1(x Wq^T)
    hgemm<false,1,false,false,false,true,false><<<dim3(4,128,1),256,SMEMSZ>>>(
        xh, Wqh, Qh, nullptr, nullptr, DD, DD, DD, DD, 0, 0,0,0,0);
    // 2) K = elu1(x Wk^T)  (normal + transposed Kt[D, NTOK])
    hgemm<false,1,false,false,false,true,true><<<dim3(4,128,1),256,SMEMSZ>>>(
        xh, Wkh, Kh, Kth, nullptr, DD, DD, DD, DD, NTOK, 0,0,0,0);
    // 3) Vt = (x Wv^T)^T   (transposed only)
    hgemm<false,0,false,false,false,false,true><<<dim3(4,128,1),256,SMEMSZ>>>(
        xh, Wvh, nullptr, Vth, nullptr, DD, DD, DD, 0, NTOK, 0,0,0,0);
    // 4) St_c[dm,dk] = Vt_c · Kt_c^T
    hgemm<false,0,false,false,false,true,false><<<dim3(4,8,NCHUNK),256,SMEMSZ>>>(
        Vth, Kth, Sh, nullptr, nullptr, CTOK, NTOK, NTOK, DD, 0,
        (long)CTOK, (long)CTOK, (long)DD*DD, 0);
    // 5) exclusive prefix over chunks
    prefix_kernel<<<DD*DD/256, 256>>>(Sh);
    // 6) denominator path (parallel 2-pass cumsum, then dot)
    kchunksum_kernel<<<NCHUNK*BB*DD/256, 256>>>(Kh, Zc);
    kcum2_kernel<<<NCHUNK*BB*DD/256, 256>>>(Kh, Zc, Kc);
    denom_kernel<<<NTOK/8, 256>>>(Qh, Kc, Dn);
    // 7) Y1 = Q_c · Sprefix_c^T   (fp32 out)
    hgemm<true,0,false,false,false,true,false><<<dim3(4,4,NCHUNK),256,SMEMSZ>>>(
        Qh, Sh, out, nullptr, nullptr, DD, DD, DD, DD, 0,
        (long)CTOK*DD, (long)DD*DD, (long)CTOK*DD, 0);
    // 8) P = mask(Q_c · K_c^T)  (fully-masked tiles short-circuited)
    hgemm<false,0,true,false,false,true,false><<<dim3(2,4,NCHUNK),256,SMEMSZ>>>(
        Qh, Kh, Ph, nullptr, nullptr, DD, DD, DD, CTOK, 0,
        (long)CTOK*DD, (long)CTOK*DD, (long)CTOK*CTOK, 0);
    // 9) Y += P_c · Vt_c^T, then / denom  (fp32 out)
    hgemm<true,0,false,true,true,true,false><<<dim3(4,4,NCHUNK),256,SMEMSZ>>>(
        Ph, Vth, out, nullptr, Dn, CTOK, CTOK, NTOK, DD, 0,
        (long)CTOK*CTOK, (long)CTOK, (long)CTOK*DD, 0);
}

// round 13
// speedup vs baseline: 1.1193x; 1.1077x over previous
#include <cuda_runtime.h>
#include <cuda_fp16.h>
#include <math.h>
#include <stdint.h>

#define TT 4096
#define BB 4
#define DD 1024
#define NTOK (TT*BB)
#define CTOK 512
#define NCHUNK 32

// -------- scratch (fp16 intermediates) --------
__device__ __align__(128) __half g_xh[(size_t)NTOK*DD];
__device__ __align__(128) __half g_Wh[(size_t)3*DD*DD];
__device__ __align__(128) __half g_Q [(size_t)NTOK*DD];
__device__ __align__(128) __half g_K [(size_t)NTOK*DD];
__device__ __align__(128) __half g_Kt[(size_t)DD*NTOK];
__device__ __align__(128) __half g_Vt[(size_t)DD*NTOK];
__device__ __align__(128) __half g_S [(size_t)NCHUNK*DD*DD];
__device__ __align__(128) __half g_P [(size_t)NCHUNK*CTOK*CTOK];
__device__ float g_Zc[(size_t)NCHUNK*BB*DD];
__device__ float g_Kc[(size_t)NTOK*DD];
__device__ float g_Dn[NTOK];

#define RSB   80                 // smem row stride bytes (32 halves + pad)
#define ATILE 10240              // 128 rows * 80B
#define BTILE 20480              // 256 rows * 80B
#define STAGE (ATILE + BTILE)    // 30720
#define NSTG  4
#define SMEMSZ (NSTG*STAGE)      // 122880

__device__ __forceinline__ uint32_t smem_u32(const void* p){
    uint32_t a; asm("{ .reg .u64 t; cvta.to.shared.u64 t, %1; cvt.u32.u64 %0, t; }":"=r"(a):"l"(p)); return a;
}
__device__ __forceinline__ void cp16(uint32_t s, const void* g){
    asm volatile("cp.async.cg.shared.global [%0], [%1], 16;" :: "r"(s), "l"(g));
}

// shared staging helper macros (identical math to R8 core)
#define STAGE_DECL                                                            \
    const int a0 = tid*2, a1 = tid*2 + 1;                                     \
    const int b0 = tid*4;                                                     \
    const uint32_t acs0 = sbase + (a0>>2)*RSB + (a0&3)*16;                    \
    const uint32_t acs1 = sbase + (a1>>2)*RSB + (a1&3)*16;                    \
    const uint32_t bcs0 = sbase + ATILE + ((b0  )>>2)*RSB + ((b0  )&3)*16;    \
    const uint32_t bcs1 = sbase + ATILE + ((b0+1)>>2)*RSB + ((b0+1)&3)*16;    \
    const uint32_t bcs2 = sbase + ATILE + ((b0+2)>>2)*RSB + ((b0+2)&3)*16;    \
    const uint32_t bcs3 = sbase + ATILE + ((b0+3)>>2)*RSB + ((b0+3)&3)*16;    \
    const __half *acp0, *acp1, *bcp0, *bcp1, *bcp2, *bcp3;

#define STAGE_SETUP(Abase, lda_, Bbase, ldb_)                                 \
    acp0 = (Abase) + (long)(row0 + (a0>>2))*(lda_) + (a0&3)*8;                \
    acp1 = (Abase) + (long)(row0 + (a1>>2))*(lda_) + (a1&3)*8;                \
    bcp0 = (Bbase) + (long)(col0 + ((b0  )>>2))*(ldb_) + ((b0  )&3)*8;        \
    bcp1 = (Bbase) + (long)(col0 + ((b0+1)>>2))*(ldb_) + ((b0+1)&3)*8;       \
    bcp2 = (Bbase) + (long)(col0 + ((b0+2)>>2))*(ldb_) + ((b0+2)&3)*8;       \
    bcp3 = (Bbase) + (long)(col0 + ((b0+3)>>2))*(ldb_) + ((b0+3)&3)*8;

#define FRAG_DECL                                                             \
    const uint32_t a_lm = (uint32_t)(wm*64*RSB + (lane&15)*RSB + (lane>>4)*16); \
    const uint32_t b_lm = (uint32_t)(ATILE + wn*64*RSB                        \
                        + ((lane&7) + ((lane>>4)&1)*8)*RSB + ((lane>>3)&1)*16);

#define DEF_LOADCP                                                            \
    auto loadcp = [&](int st, int k0){                                        \
        uint32_t so = st*STAGE;                                               \
        cp16(acs0 + so, acp0 + k0);                                           \
        cp16(acs1 + so, acp1 + k0);                                           \
        cp16(bcs0 + so, bcp0 + k0);                                           \
        cp16(bcs1 + so, bcp1 + k0);                                           \
        cp16(bcs2 + so, bcp2 + k0);                                           \
        cp16(bcs3 + so, bcp3 + k0);                                           \
        asm volatile("cp.async.commit_group;" ::: "memory");                  \
    };

#define DEF_MMASTAGE                                                          \
    auto mma_stage = [&](int st){                                             \
        uint32_t base = sbase + st*STAGE;                                     \
        _Pragma("unroll")                                                     \
        for (int kk = 0; kk < 2; kk++){                                       \
            uint32_t af[4][4], bf[8][2];                                      \
            _Pragma("unroll")                                                 \
            for (int mt = 0; mt < 4; mt++){                                   \
                uint32_t ad = base + a_lm + mt*(16*RSB) + kk*32;              \
                asm volatile("ldmatrix.sync.aligned.m8n8.x4.shared.b16 {%0,%1,%2,%3},[%4];" \
                    : "=r"(af[mt][0]),"=r"(af[mt][1]),"=r"(af[mt][2]),"=r"(af[mt][3]) \
                    : "r"(ad));                                               \
            }                                                                 \
            _Pragma("unroll")                                                 \
            for (int p = 0; p < 4; p++){                                      \
                uint32_t bd = base + b_lm + p*(16*RSB) + kk*32;               \
                uint32_t r0,r1,r2,r3;                                         \
                asm volatile("ldmatrix.sync.aligned.m8n8.x4.shared.b16 {%0,%1,%2,%3},[%4];" \
                    : "=r"(r0),"=r"(r1),"=r"(r2),"=r"(r3) : "r"(bd));         \
                bf[2*p][0]=r0; bf[2*p][1]=r1; bf[2*p+1][0]=r2; bf[2*p+1][1]=r3; \
            }                                                                 \
            _Pragma("unroll")                                                 \
            for (int mt = 0; mt < 4; mt++)                                    \
                _Pragma("unroll")                                             \
                for (int nt = 0; nt < 8; nt++)                                \
                    asm volatile(                                             \
                        "mma.sync.aligned.m16n8k16.row.col.f32.f16.f16.f32 "  \
                        "{%0,%1,%2,%3},{%4,%5,%6,%7},{%8,%9},{%0,%1,%2,%3};"  \
                        : "+f"(acc[mt][nt][0]),"+f"(acc[mt][nt][1]),          \
                          "+f"(acc[mt][nt][2]),"+f"(acc[mt][nt][3])           \
                        : "r"(af[mt][0]),"r"(af[mt][1]),"r"(af[mt][2]),"r"(af[mt][3]), \
                          "r"(bf[nt][0]),"r"(bf[nt][1]));                     \
        }                                                                     \
    };

#define DEF_PIPELINE                                                          \
    auto run_pipeline = [&](int n){                                           \
        loadcp(0, 0);                                                         \
        loadcp(1, 32);                                                        \
        loadcp(2, 64);                                                        \
        for (int s = 0; s < n; s++){                                          \
            if (s < n-2)       asm volatile("cp.async.wait_group 2;" ::: "memory"); \
            else if (s == n-2) asm volatile("cp.async.wait_group 1;" ::: "memory"); \
            else               asm volatile("cp.async.wait_group 0;" ::: "memory"); \
            __syncthreads();                                                  \
            if (s + 3 < n) loadcp((s+3)&3, (s+3)*32);                         \
            mma_stage(s & 3);                                                 \
        }                                                                     \
    };

// =====================================================================
// generic NT GEMM (R8 core): used for step 4 (plain) and step 8 (mask)
// =====================================================================
template<int ACT, bool MASK>
__global__ void __launch_bounds__(256, 1) hgemm(
    const __half* __restrict__ A, const __half* __restrict__ B,
    __half* __restrict__ C,
    int K, int lda, int ldb, int ldc,
    long sA, long sB, long sC)
{
    extern __shared__ char smem[];
    const uint32_t sbase = smem_u32(smem);
    const int tid  = threadIdx.x;
    const int lane = tid & 31;
    const int warp = tid >> 5;
    const int wm = warp >> 2, wn = warp & 3;
    const int gid = lane >> 2, tig = lane & 3;
    const int bz = blockIdx.z;
    const int row0 = blockIdx.y * 128;
    const int col0 = blockIdx.x * 256;

    const __half* Ah = A + (long)bz*sA;
    const __half* Bh = B + (long)bz*sB;
    __half* Chh = C + (long)bz*sC;

    // fully-masked tile: write zeros and exit
    if (MASK){
        if ((col0 >> 2) > ((row0 + 127) >> 2)){
            #pragma unroll
            for (int it = 0; it < 16; it++){
                int task = it*256 + tid;
                int r = task >> 5, ch = task & 31;
                uint4 z = make_uint4(0,0,0,0);
                *(uint4*)&Chh[(long)(row0 + r)*ldc + col0 + ch*8] = z;
            }
            return;
        }
    }

    float acc[4][8][4] = {};
    FRAG_DECL
    STAGE_DECL
    STAGE_SETUP(Ah, lda, Bh, ldb)
    DEF_LOADCP
    DEF_MMASTAGE
    DEF_PIPELINE

    run_pipeline(K >> 5);

    #pragma unroll
    for (int mt = 0; mt < 4; mt++){
        int r0 = row0 + wm*64 + mt*16 + gid;
        int r1 = r0 + 8;
        #pragma unroll
        for (int nt = 0; nt < 8; nt++){
            int c0 = col0 + wn*64 + nt*8 + 2*tig;
            float v[4];
            #pragma unroll
            for (int e = 0; e < 4; e++){
                float f = acc[mt][nt][e];
                if (ACT == 1) f = (f > 0.0f) ? (f + 1.0f) : expf(f);
                if (MASK){
                    int r = (e < 2) ? r0 : r1;
                    int c = c0 + (e & 1);
                    if ((c >> 2) > (r >> 2)) f = 0.0f;
                }
                v[e] = f;
            }
            *(__half2*)(Chh + (long)r0*ldc + c0) = __floats2half2_rn(v[0], v[1]);
            *(__half2*)(Chh + (long)r1*ldc + c0) = __floats2half2_rn(v[2], v[3]);
        }
    }
}

// =====================================================================
// fused Q/K/V projection: grid (12,128); x>>2 selects matrix, epilogues
// Q: elu1 -> Qh ;  K: elu1 -> Kh + Kth^T ;  V: -> Vth^T only
// =====================================================================
__global__ void __launch_bounds__(256, 1) proj_kernel(
    const __half* __restrict__ xh, const __half* __restrict__ Wall,
    __half* __restrict__ Qh, __half* __restrict__ Kh,
    __half* __restrict__ Kth, __half* __restrict__ Vth)
{
    extern __shared__ char smem[];
    const uint32_t sbase = smem_u32(smem);
    const int tid  = threadIdx.x;
    const int lane = tid & 31;
    const int warp = tid >> 5;
    const int wm = warp >> 2, wn = warp & 3;
    const int gid = lane >> 2, tig = lane & 3;
    const int m    = blockIdx.x >> 2;            // 0=Q 1=K 2=V
    const int col0 = (blockIdx.x & 3) * 256;
    const int row0 = blockIdx.y * 128;

    const __half* Ah = xh;
    const __half* Bh = Wall + (size_t)m*DD*DD;

    float acc[4][8][4] = {};
    FRAG_DECL
    STAGE_DECL
    STAGE_SETUP(Ah, DD, Bh, DD)
    DEF_LOADCP
    DEF_MMASTAGE
    DEF_PIPELINE

    run_pipeline(DD >> 5);

    const bool act = (m < 2);
    __half* Cn = (m == 0) ? Qh : Kh;             // row-major dest (m<=1)
    __half* Ct = (m == 1) ? Kth : Vth;           // transposed dest (m>=1)

    #pragma unroll
    for (int mt = 0; mt < 4; mt++){
        int r0 = row0 + wm*64 + mt*16 + gid;
        int r1 = r0 + 8;
        #pragma unroll
        for (int nt = 0; nt < 8; nt++){
            int c0 = col0 + wn*64 + nt*8 + 2*tig;
            float v[4];
            #pragma unroll
            for (int e = 0; e < 4; e++){
                float f = acc[mt][nt][e];
                if (act) f = (f > 0.0f) ? (f + 1.0f) : expf(f);
                v[e] = f;
            }
            if (m <= 1){
                *(__half2*)(Cn + (long)r0*DD + c0) = __floats2half2_rn(v[0], v[1]);
                *(__half2*)(Cn + (long)r1*DD + c0) = __floats2half2_rn(v[2], v[3]);
            }
            if (m >= 1){
                Ct[(long)(c0  )*NTOK + r0] = __float2half(v[0]);
                Ct[(long)(c0+1)*NTOK + r0] = __float2half(v[1]);
                Ct[(long)(c0  )*NTOK + r1] = __float2half(v[2]);
                Ct[(long)(c0+1)*NTOK + r1] = __float2half(v[3]);
            }
        }
    }
}

// =====================================================================
// fused steps 7+9: Y = (Q_c·Sprefix_c^T + P_c·Vt_c^T) / denom  (fp32 out)
// grid (4,4,32)
// =====================================================================
__global__ void __launch_bounds__(256, 1) fused79_kernel(
    const __half* __restrict__ Qh, const __half* __restrict__ Sh,
    const __half* __restrict__ Ph, const __half* __restrict__ Vth,
    const float* __restrict__ Dn, float* __restrict__ out)
{
    extern __shared__ char smem[];
    const uint32_t sbase = smem_u32(smem);
    const int tid  = threadIdx.x;
    const int lane = tid & 31;
    const int warp = tid >> 5;
    const int wm = warp >> 2, wn = warp & 3;
    const int gid = lane >> 2, tig = lane & 3;
    const int bz = blockIdx.z;
    const int row0 = blockIdx.y * 128;
    const int col0 = blockIdx.x * 256;

    float acc[4][8][4] = {};
    FRAG_DECL
    STAGE_DECL
    DEF_LOADCP
    DEF_MMASTAGE
    DEF_PIPELINE

    // phase 0: Q_c [CTOK,DD] · S_c [DD,DD]^T   (K = DD)
    STAGE_SETUP(Qh + (long)bz*CTOK*DD, DD, Sh + (size_t)bz*DD*DD, DD)
    run_pipeline(DD >> 5);

    // phase 1: P_c [CTOK,CTOK] · Vt_c [DD, CTOK]^T  (K = CTOK)
    STAGE_SETUP(Ph + (size_t)bz*CTOK*CTOK, CTOK, Vth + (long)bz*CTOK, NTOK)
    run_pipeline(CTOK >> 5);

    float* Cf = out + (long)bz*CTOK*DD;
    #pragma unroll
    for (int mt = 0; mt < 4; mt++){
        int r0 = row0 + wm*64 + mt*16 + gid;
        int r1 = r0 + 8;
        float dn0 = Dn[(long)bz*CTOK + r0];
        float dn1 = Dn[(long)bz*CTOK + r1];
        #pragma unroll
        for (int nt = 0; nt < 8; nt++){
            int c0 = col0 + wn*64 + nt*8 + 2*tig;
            float2 p0 = make_float2(acc[mt][nt][0]/dn0, acc[mt][nt][1]/dn0);
            float2 p1 = make_float2(acc[mt][nt][2]/dn1, acc[mt][nt][3]/dn1);
            *(float2*)(Cf + (long)r0*DD + c0) = p0;
            *(float2*)(Cf + (long)r1*DD + c0) = p1;
        }
    }
}

// -------- fp32 -> fp16 conversion (R8 version) --------
__global__ void f2h_kernel(const float* __restrict__ in, __half* __restrict__ out, int n8)
{
    int i = blockIdx.x * blockDim.x + threadIdx.x;
    if (i >= n8) return;
    float4 a = ((const float4*)in)[2*i];
    float4 b = ((const float4*)in)[2*i+1];
    __half2 h[4] = { __floats2half2_rn(a.x,a.y), __floats2half2_rn(a.z,a.w),
                     __floats2half2_rn(b.x,b.y), __floats2half2_rn(b.z,b.w) };
    ((uint4*)out)[i] = *(uint4*)h;
}

// -------- aux kernels --------
__global__ void prefix_kernel(__half* __restrict__ S)
{
    long e = (long)blockIdx.x * blockDim.x + threadIdx.x;
    float acc = 0.0f;
    for (int c = 0; c < NCHUNK; c++){
        long off = (long)c * DD * DD + e;
        float v = __half2float(S[off]);
        S[off] = __float2half(acc);
        acc += v;
    }
}
__global__ void kchunksum_kernel(const __half* __restrict__ Kp, float* __restrict__ Zc)
{
    int id = blockIdx.x * blockDim.x + threadIdx.x;   // < NCHUNK*4096
    int c = id >> 12, bd = id & 4095;
    const __half* p = Kp + (long)c*128*4096 + bd;
    float s = 0.0f;
    #pragma unroll 8
    for (int t = 0; t < 128; t++) s += __half2float(p[(long)t*4096]);
    Zc[id] = s;
}
__global__ void kcum2_kernel(const __half* __restrict__ Kp,
                             const float* __restrict__ Zc,
                             float* __restrict__ Kc)
{
    int id = blockIdx.x * blockDim.x + threadIdx.x;   // < NCHUNK*4096
    int c = id >> 12, bd = id & 4095;
    float acc = 0.0f;
    for (int cp = 0; cp < c; cp++) acc += Zc[cp*4096 + bd];
    const __half* p = Kp + (long)c*128*4096 + bd;
    float*       o = Kc + (long)c*128*4096 + bd;
    #pragma unroll 4
    for (int t = 0; t < 128; t++){
        acc += __half2float(p[(long)t*4096]);
        o[(long)t*4096] = acc;
    }
}
__global__ void denom_kernel(const __half* __restrict__ Qp,
                             const float* __restrict__ Kc,
                             float* __restrict__ dn)
{
    int warp = (blockIdx.x * blockDim.x + threadIdx.x) >> 5;
    int lane = threadIdx.x & 31;
    if (warp >= NTOK) return;
    const __half* qv = Qp + (long)warp * DD;
    const float*  zv = Kc + (long)warp * DD;
    float s = 0.0f;
    for (int d = lane; d < DD; d += 32) s += __half2float(qv[d]) * zv[d];
    #pragma unroll
    for (int o = 16; o; o >>= 1) s += __shfl_down_sync(0xffffffffu, s, o);
    if (lane == 0) dn[warp] = s;
}

extern "C" void kernel_launch(void* const* d_in, const int* in_sizes, int n_in,
                              void* d_out, int out_size)
{
    const float* x  = (const float*)d_in[0];
    const float* Wq = (const float*)d_in[1];
    const float* Wk = (const float*)d_in[2];
    const float* Wv = (const float*)d_in[3];
    float* out = (float*)d_out;

    __half *xh,*Wh,*Qh,*Kh,*Kth,*Vth,*Sh,*Ph; float *Zc,*Kc,*Dn;
    cudaGetSymbolAddress((void**)&xh,  g_xh);
    cudaGetSymbolAddress((void**)&Wh,  g_Wh);
    cudaGetSymbolAddress((void**)&Qh,  g_Q);
    cudaGetSymbolAddress((void**)&Kh,  g_K);
    cudaGetSymbolAddress((void**)&Kth, g_Kt);
    cudaGetSymbolAddress((void**)&Vth, g_Vt);
    cudaGetSymbolAddress((void**)&Sh,  g_S);
    cudaGetSymbolAddress((void**)&Ph,  g_P);
    cudaGetSymbolAddress((void**)&Zc,  g_Zc);
    cudaGetSymbolAddress((void**)&Kc,  g_Kc);
    cudaGetSymbolAddress((void**)&Dn,  g_Dn);
    __half *Wqh = Wh, *Wkh = Wh + (size_t)DD*DD, *Wvh = Wh + (size_t)2*DD*DD;

    cudaFuncSetAttribute(hgemm<0,false>, cudaFuncAttributeMaxDynamicSharedMemorySize, SMEMSZ);
    cudaFuncSetAttribute(hgemm<0,true >, cudaFuncAttributeMaxDynamicSharedMemorySize, SMEMSZ);
    cudaFuncSetAttribute(proj_kernel,    cudaFuncAttributeMaxDynamicSharedMemorySize, SMEMSZ);
    cudaFuncSetAttribute(fused79_kernel, cudaFuncAttributeMaxDynamicSharedMemorySize, SMEMSZ);

    // 0) convert inputs to fp16 (W packed as [Wq|Wk|Wv])
    f2h_kernel<<<((size_t)NTOK*DD/8 + 255)/256, 256>>>(x,  xh,  NTOK*DD/8);
    f2h_kernel<<<(DD*DD/8 + 255)/256, 256>>>(Wq, Wqh, DD*DD/8);
    f2h_kernel<<<(DD*DD/8 + 255)/256, 256>>>(Wk, Wkh, DD*DD/8);
    f2h_kernel<<<(DD*DD/8 + 255)/256, 256>>>(Wv, Wvh, DD*DD/8);

    // 1) fused projections: Q, K (+Kt), Vt
    proj_kernel<<<dim3(12,128,1),256,SMEMSZ>>>(xh, Wh, Qh, Kh, Kth, Vth);

    // 2) St_c[dm,dk] = Vt_c · Kt_c^T
    hgemm<0,false><<<dim3(4,8,NCHUNK),256,SMEMSZ>>>(
        Vth, Kth, Sh, CTOK, NTOK, NTOK, DD,
        (long)CTOK, (long)CTOK, (long)DD*DD);

    // 3) exclusive prefix over chunks
    prefix_kernel<<<DD*DD/256, 256>>>(Sh);

    // 4) denominator path (parallel 2-pass cumsum, then dot)
    kchunksum_kernel<<<NCHUNK*BB*DD/256, 256>>>(Kh, Zc);
    kcum2_kernel<<<NCHUNK*BB*DD/256, 256>>>(Kh, Zc, Kc);
    denom_kernel<<<NTOK/8, 256>>>(Qh, Kc, Dn);

    // 5) P = mask(Q_c · K_c^T)  (fully-masked tiles short-circuited)
    hgemm<0,true><<<dim3(2,4,NCHUNK),256,SMEMSZ>>>(
        Qh, Kh, Ph, DD, DD, DD, CTOK,
        (long)CTOK*DD, (long)CTOK*DD, (long)CTOK*CTOK);

    // 6) Y = (Q_c·Sprefix^T + P_c·Vt^T) / denom
    fused79_kernel<<<dim3(4,4,NCHUNK),256,SMEMSZ>>>(Qh, Sh, Ph, Vth, Dn, out);
}

// round 14
// speedup vs baseline: 1.1248x; 1.0049x over previous
#include <cuda_runtime.h>
#include <cuda_fp16.h>
#include <math.h>
#include <stdint.h>

#define TT 4096
#define BB 4
#define DD 1024
#define NTOK (TT*BB)
#define CTOK 512
#define NCHUNK 32

// -------- scratch (fp16 intermediates) --------
__device__ __align__(128) __half g_xh[(size_t)NTOK*DD];
__device__ __align__(128) __half g_Wh[(size_t)3*DD*DD];
__device__ __align__(128) __half g_Q [(size_t)NTOK*DD];
__device__ __align__(128) __half g_K [(size_t)NTOK*DD];
__device__ __align__(128) __half g_Kt[(size_t)DD*NTOK];
__device__ __align__(128) __half g_Vt[(size_t)DD*NTOK];
__device__ __align__(128) __half g_S [(size_t)NCHUNK*DD*DD];
__device__ __align__(128) __half g_P [(size_t)NCHUNK*CTOK*CTOK];
__device__ float g_Zc[(size_t)NCHUNK*BB*DD];
__device__ float g_Dn[NTOK];

#define RSB   80                 // smem row stride bytes (32 halves + pad)
#define ATILE 10240              // 128 rows * 80B
#define BTILE 20480              // 256 rows * 80B
#define STAGE (ATILE + BTILE)    // 30720
#define NSTG  4
#define SMEMSZ (NSTG*STAGE)      // 122880

__device__ __forceinline__ uint32_t smem_u32(const void* p){
    uint32_t a; asm("{ .reg .u64 t; cvta.to.shared.u64 t, %1; cvt.u32.u64 %0, t; }":"=r"(a):"l"(p)); return a;
}
__device__ __forceinline__ void cp16(uint32_t s, const void* g){
    asm volatile("cp.async.cg.shared.global [%0], [%1], 16;" :: "r"(s), "l"(g));
}

// shared staging helper macros (identical math to R8 core)
#define STAGE_DECL                                                            \
    const int a0 = tid*2, a1 = tid*2 + 1;                                     \
    const int b0 = tid*4;                                                     \
    const uint32_t acs0 = sbase + (a0>>2)*RSB + (a0&3)*16;                    \
    const uint32_t acs1 = sbase + (a1>>2)*RSB + (a1&3)*16;                    \
    const uint32_t bcs0 = sbase + ATILE + ((b0  )>>2)*RSB + ((b0  )&3)*16;    \
    const uint32_t bcs1 = sbase + ATILE + ((b0+1)>>2)*RSB + ((b0+1)&3)*16;    \
    const uint32_t bcs2 = sbase + ATILE + ((b0+2)>>2)*RSB + ((b0+2)&3)*16;    \
    const uint32_t bcs3 = sbase + ATILE + ((b0+3)>>2)*RSB + ((b0+3)&3)*16;    \
    const __half *acp0, *acp1, *bcp0, *bcp1, *bcp2, *bcp3;

#define STAGE_SETUP(Abase, lda_, Bbase, ldb_)                                 \
    acp0 = (Abase) + (long)(row0 + (a0>>2))*(lda_) + (a0&3)*8;                \
    acp1 = (Abase) + (long)(row0 + (a1>>2))*(lda_) + (a1&3)*8;                \
    bcp0 = (Bbase) + (long)(col0 + ((b0  )>>2))*(ldb_) + ((b0  )&3)*8;        \
    bcp1 = (Bbase) + (long)(col0 + ((b0+1)>>2))*(ldb_) + ((b0+1)&3)*8;       \
    bcp2 = (Bbase) + (long)(col0 + ((b0+2)>>2))*(ldb_) + ((b0+2)&3)*8;       \
    bcp3 = (Bbase) + (long)(col0 + ((b0+3)>>2))*(ldb_) + ((b0+3)&3)*8;

#define FRAG_DECL                                                             \
    const uint32_t a_lm = (uint32_t)(wm*64*RSB + (lane&15)*RSB + (lane>>4)*16); \
    const uint32_t b_lm = (uint32_t)(ATILE + wn*64*RSB                        \
                        + ((lane&7) + ((lane>>4)&1)*8)*RSB + ((lane>>3)&1)*16);

#define DEF_LOADCP                                                            \
    auto loadcp = [&](int st, int k0){                                        \
        uint32_t so = st*STAGE;                                               \
        cp16(acs0 + so, acp0 + k0);                                           \
        cp16(acs1 + so, acp1 + k0);                                           \
        cp16(bcs0 + so, bcp0 + k0);                                           \
        cp16(bcs1 + so, bcp1 + k0);                                           \
        cp16(bcs2 + so, bcp2 + k0);                                           \
        cp16(bcs3 + so, bcp3 + k0);                                           \
        asm volatile("cp.async.commit_group;" ::: "memory");                  \
    };

#define DEF_MMASTAGE                                                          \
    auto mma_stage = [&](int st){                                             \
        uint32_t base = sbase + st*STAGE;                                     \
        _Pragma("unroll")                                                     \
        for (int kk = 0; kk < 2; kk++){                                       \
            uint32_t af[4][4], bf[8][2];                                      \
            _Pragma("unroll")                                                 \
            for (int mt = 0; mt < 4; mt++){                                   \
                uint32_t ad = base + a_lm + mt*(16*RSB) + kk*32;              \
                asm volatile("ldmatrix.sync.aligned.m8n8.x4.shared.b16 {%0,%1,%2,%3},[%4];" \
                    : "=r"(af[mt][0]),"=r"(af[mt][1]),"=r"(af[mt][2]),"=r"(af[mt][3]) \
                    : "r"(ad));                                               \
            }                                                                 \
            _Pragma("unroll")                                                 \
            for (int p = 0; p < 4; p++){                                      \
                uint32_t bd = base + b_lm + p*(16*RSB) + kk*32;               \
                uint32_t r0,r1,r2,r3;                                         \
                asm volatile("ldmatrix.sync.aligned.m8n8.x4.shared.b16 {%0,%1,%2,%3},[%4];" \
                    : "=r"(r0),"=r"(r1),"=r"(r2),"=r"(r3) : "r"(bd));         \
                bf[2*p][0]=r0; bf[2*p][1]=r1; bf[2*p+1][0]=r2; bf[2*p+1][1]=r3; \
            }                                                                 \
            _Pragma("unroll")                                                 \
            for (int mt = 0; mt < 4; mt++)                                    \
                _Pragma("unroll")                                             \
                for (int nt = 0; nt < 8; nt++)                                \
                    asm volatile(                                             \
                        "mma.sync.aligned.m16n8k16.row.col.f32.f16.f16.f32 "  \
                        "{%0,%1,%2,%3},{%4,%5,%6,%7},{%8,%9},{%0,%1,%2,%3};"  \
                        : "+f"(acc[mt][nt][0]),"+f"(acc[mt][nt][1]),          \
                          "+f"(acc[mt][nt][2]),"+f"(acc[mt][nt][3])           \
                        : "r"(af[mt][0]),"r"(af[mt][1]),"r"(af[mt][2]),"r"(af[mt][3]), \
                          "r"(bf[nt][0]),"r"(bf[nt][1]));                     \
        }                                                                     \
    };

#define DEF_PIPELINE                                                          \
    auto run_pipeline = [&](int n){                                           \
        loadcp(0, 0);                                                         \
        loadcp(1, 32);                                                        \
        loadcp(2, 64);                                                        \
        for (int s = 0; s < n; s++){                                          \
            if (s < n-2)       asm volatile("cp.async.wait_group 2;" ::: "memory"); \
            else if (s == n-2) asm volatile("cp.async.wait_group 1;" ::: "memory"); \
            else               asm volatile("cp.async.wait_group 0;" ::: "memory"); \
            __syncthreads();                                                  \
            if (s + 3 < n) loadcp((s+3)&3, (s+3)*32);                         \
            mma_stage(s & 3);                                                 \
        }                                                                     \
    };

// =====================================================================
// dual GEMM: one launch for step 4 (S = Vt·Kt^T) and step 8 (P = mask(Q·K^T))
// grid (40, NCHUNK): x<32 -> S tile (4x,8y); x>=32 -> P tile (2x,4y)
// =====================================================================
__global__ void __launch_bounds__(256, 1) dual_gemm(
    const __half* __restrict__ Vth, const __half* __restrict__ Kth,
    __half* __restrict__ Sh,
    const __half* __restrict__ Qh, const __half* __restrict__ Kh,
    __half* __restrict__ Ph)
{
    extern __shared__ char smem[];
    const uint32_t sbase = smem_u32(smem);
    const int tid  = threadIdx.x;
    const int lane = tid & 31;
    const int warp = tid >> 5;
    const int wm = warp >> 2, wn = warp & 3;
    const int gid = lane >> 2, tig = lane & 3;
    const int chunk = blockIdx.y;
    const int xid = blockIdx.x;
    const bool isP = (xid >= 32);

    const __half *Ah, *Bh; __half* Chh;
    int lda, ldb, ldc, Kdim, row0, col0;
    if (!isP){
        int xx = xid & 3, yy = xid >> 2;
        Ah = Vth + (long)chunk*CTOK;  lda = NTOK;
        Bh = Kth + (long)chunk*CTOK;  ldb = NTOK;
        Chh = Sh + (size_t)chunk*DD*DD; ldc = DD;
        Kdim = CTOK; row0 = yy*128; col0 = xx*256;
    } else {
        int t = xid - 32;
        int xx = t & 1, yy = t >> 1;
        Ah = Qh + (long)chunk*CTOK*DD; lda = DD;
        Bh = Kh + (long)chunk*CTOK*DD; ldb = DD;
        Chh = Ph + (size_t)chunk*CTOK*CTOK; ldc = CTOK;
        Kdim = DD; row0 = yy*128; col0 = xx*256;
    }

    // fully-masked P tile: write zeros and exit
    if (isP && ((col0 >> 2) > ((row0 + 127) >> 2))){
        #pragma unroll
        for (int it = 0; it < 16; it++){
            int task = it*256 + tid;
            int r = task >> 5, ch = task & 31;
            uint4 z = make_uint4(0,0,0,0);
            *(uint4*)&Chh[(long)(row0 + r)*ldc + col0 + ch*8] = z;
        }
        return;
    }

    float acc[4][8][4] = {};
    FRAG_DECL
    STAGE_DECL
    STAGE_SETUP(Ah, lda, Bh, ldb)
    DEF_LOADCP
    DEF_MMASTAGE
    DEF_PIPELINE

    run_pipeline(Kdim >> 5);

    #pragma unroll
    for (int mt = 0; mt < 4; mt++){
        int r0 = row0 + wm*64 + mt*16 + gid;
        int r1 = r0 + 8;
        #pragma unroll
        for (int nt = 0; nt < 8; nt++){
            int c0 = col0 + wn*64 + nt*8 + 2*tig;
            float v[4];
            #pragma unroll
            for (int e = 0; e < 4; e++){
                float f = acc[mt][nt][e];
                if (isP){
                    int r = (e < 2) ? r0 : r1;
                    int c = c0 + (e & 1);
                    if ((c >> 2) > (r >> 2)) f = 0.0f;
                }
                v[e] = f;
            }
            *(__half2*)(Chh + (long)r0*ldc + c0) = __floats2half2_rn(v[0], v[1]);
            *(__half2*)(Chh + (long)r1*ldc + c0) = __floats2half2_rn(v[2], v[3]);
        }
    }
}

// =====================================================================
// fused Q/K/V projection: grid (12,128)
// =====================================================================
__global__ void __launch_bounds__(256, 1) proj_kernel(
    const __half* __restrict__ xh, const __half* __restrict__ Wall,
    __half* __restrict__ Qh, __half* __restrict__ Kh,
    __half* __restrict__ Kth, __half* __restrict__ Vth)
{
    extern __shared__ char smem[];
    const uint32_t sbase = smem_u32(smem);
    const int tid  = threadIdx.x;
    const int lane = tid & 31;
    const int warp = tid >> 5;
    const int wm = warp >> 2, wn = warp & 3;
    const int gid = lane >> 2, tig = lane & 3;
    const int m    = blockIdx.x >> 2;            // 0=Q 1=K 2=V
    const int col0 = (blockIdx.x & 3) * 256;
    const int row0 = blockIdx.y * 128;

    const __half* Ah = xh;
    const __half* Bh = Wall + (size_t)m*DD*DD;

    float acc[4][8][4] = {};
    FRAG_DECL
    STAGE_DECL
    STAGE_SETUP(Ah, DD, Bh, DD)
    DEF_LOADCP
    DEF_MMASTAGE
    DEF_PIPELINE

    run_pipeline(DD >> 5);

    const bool act = (m < 2);
    __half* Cn = (m == 0) ? Qh : Kh;
    __half* Ct = (m == 1) ? Kth : Vth;

    #pragma unroll
    for (int mt = 0; mt < 4; mt++){
        int r0 = row0 + wm*64 + mt*16 + gid;
        int r1 = r0 + 8;
        #pragma unroll
        for (int nt = 0; nt < 8; nt++){
            int c0 = col0 + wn*64 + nt*8 + 2*tig;
            float v[4];
            #pragma unroll
            for (int e = 0; e < 4; e++){
                float f = acc[mt][nt][e];
                if (act) f = (f > 0.0f) ? (f + 1.0f) : expf(f);
                v[e] = f;
            }
            if (m <= 1){
                *(__half2*)(Cn + (long)r0*DD + c0) = __floats2half2_rn(v[0], v[1]);
                *(__half2*)(Cn + (long)r1*DD + c0) = __floats2half2_rn(v[2], v[3]);
            }
            if (m >= 1){
                Ct[(long)(c0  )*NTOK + r0] = __float2half(v[0]);
                Ct[(long)(c0+1)*NTOK + r0] = __float2half(v[1]);
                Ct[(long)(c0  )*NTOK + r1] = __float2half(v[2]);
                Ct[(long)(c0+1)*NTOK + r1] = __float2half(v[3]);
            }
        }
    }
}

// =====================================================================
// fused steps 7+9: Y = (Q_c·Sprefix_c^T + P_c·Vt_c^T) / denom  (fp32 out)
// =====================================================================
__global__ void __launch_bounds__(256, 1) fused79_kernel(
    const __half* __restrict__ Qh, const __half* __restrict__ Sh,
    const __half* __restrict__ Ph, const __half* __restrict__ Vth,
    const float* __restrict__ Dn, float* __restrict__ out)
{
    extern __shared__ char smem[];
    const uint32_t sbase = smem_u32(smem);
    const int tid  = threadIdx.x;
    const int lane = tid & 31;
    const int warp = tid >> 5;
    const int wm = warp >> 2, wn = warp & 3;
    const int gid = lane >> 2, tig = lane & 3;
    const int bz = blockIdx.z;
    const int row0 = blockIdx.y * 128;
    const int col0 = blockIdx.x * 256;

    float acc[4][8][4] = {};
    FRAG_DECL
    STAGE_DECL
    DEF_LOADCP
    DEF_MMASTAGE
    DEF_PIPELINE

    STAGE_SETUP(Qh + (long)bz*CTOK*DD, DD, Sh + (size_t)bz*DD*DD, DD)
    run_pipeline(DD >> 5);

    STAGE_SETUP(Ph + (size_t)bz*CTOK*CTOK, CTOK, Vth + (long)bz*CTOK, NTOK)
    run_pipeline(CTOK >> 5);

    float* Cf = out + (long)bz*CTOK*DD;
    #pragma unroll
    for (int mt = 0; mt < 4; mt++){
        int r0 = row0 + wm*64 + mt*16 + gid;
        int r1 = r0 + 8;
        float dn0 = Dn[(long)bz*CTOK + r0];
        float dn1 = Dn[(long)bz*CTOK + r1];
        #pragma unroll
        for (int nt = 0; nt < 8; nt++){
            int c0 = col0 + wn*64 + nt*8 + 2*tig;
            float2 p0 = make_float2(acc[mt][nt][0]/dn0, acc[mt][nt][1]/dn0);
            float2 p1 = make_float2(acc[mt][nt][2]/dn1, acc[mt][nt][3]/dn1);
            *(float2*)(Cf + (long)r0*DD + c0) = p0;
            *(float2*)(Cf + (long)r1*DD + c0) = p1;
        }
    }
}

// -------- single-launch fp32 -> fp16 conversion (x | Wq | Wk | Wv) --------
#define N8X (NTOK*DD/8)
#define N8W (DD*DD/8)
__global__ void f2h_all_kernel(const float* __restrict__ x,
                               const float* __restrict__ Wq,
                               const float* __restrict__ Wk,
                               const float* __restrict__ Wv,
                               __half* __restrict__ xh, __half* __restrict__ Wh)
{
    int i = blockIdx.x * blockDim.x + threadIdx.x;
    const float* src; __half* dst; int l;
    if (i < N8X)            { src = x;  dst = xh;            l = i; }
    else if (i < N8X+N8W)   { src = Wq; dst = Wh;            l = i - N8X; }
    else if (i < N8X+2*N8W) { src = Wk; dst = Wh + (size_t)DD*DD;   l = i - N8X - N8W; }
    else if (i < N8X+3*N8W) { src = Wv; dst = Wh + (size_t)2*DD*DD; l = i - N8X - 2*N8W; }
    else return;
    float4 a = ((const float4*)src)[2*l];
    float4 b = ((const float4*)src)[2*l+1];
    __half2 h[4] = { __floats2half2_rn(a.x,a.y), __floats2half2_rn(a.z,a.w),
                     __floats2half2_rn(b.x,b.y), __floats2half2_rn(b.z,b.w) };
    ((uint4*)dst)[l] = *(uint4*)h;
}

// -------- aux kernels --------
__global__ void prefix_kernel(__half* __restrict__ S)
{
    long e = (long)blockIdx.x * blockDim.x + threadIdx.x;
    float acc = 0.0f;
    for (int c = 0; c < NCHUNK; c++){
        long off = (long)c * DD * DD + e;
        float v = __half2float(S[off]);
        S[off] = __float2half(acc);
        acc += v;
    }
}
__global__ void kchunksum_kernel(const __half* __restrict__ Kp, float* __restrict__ Zc)
{
    int id = blockIdx.x * blockDim.x + threadIdx.x;   // < NCHUNK*4096
    int c = id >> 12, bd = id & 4095;
    const __half* p = Kp + (long)c*128*4096 + bd;
    float s = 0.0f;
    #pragma unroll 8
    for (int t = 0; t < 128; t++) s += __half2float(p[(long)t*4096]);
    Zc[id] = s;
}
// fused cumsum+dot: Dn[token] = Q[token] . zcum[token]  (no Kc materialization)
// grid: 128 blocks = (chunk, b); 1024 threads = d
__global__ void __launch_bounds__(1024) zdot_kernel(
    const __half* __restrict__ Kp, const __half* __restrict__ Qp,
    const float* __restrict__ Zc, float* __restrict__ Dn)
{
    __shared__ float part[128][33];
    const int c = blockIdx.x >> 2;
    const int b = blockIdx.x & 3;
    const int d = threadIdx.x;
    const int lane = d & 31, w = d >> 5;

    float acc = 0.0f;
    for (int cp = 0; cp < c; cp++) acc += Zc[cp*4096 + b*1024 + d];

    const long base = ((long)(c*128)*4 + b)*1024 + d;   // token (c*128+t)*4+b row start
    #pragma unroll 4
    for (int t = 0; t < 128; t++){
        long off = base + (long)t*4096;
        acc += __half2float(Kp[off]);
        float s = __half2float(Qp[off]) * acc;
        #pragma unroll
        for (int o = 16; o; o >>= 1) s += __shfl_down_sync(0xffffffffu, s, o);
        if (lane == 0) part[t][w] = s;
    }
    __syncthreads();
    // 128 rows x 32 partials; threads 0..127 finish one row each
    if (d < 128){
        float s = 0.0f;
        #pragma unroll
        for (int i = 0; i < 32; i++) s += part[d][i];
        Dn[((long)(c*128 + d))*4 + b] = s;
    }
}

extern "C" void kernel_launch(void* const* d_in, const int* in_sizes, int n_in,
                              void* d_out, int out_size)
{
    const float* x  = (const float*)d_in[0];
    const float* Wq = (const float*)d_in[1];
    const float* Wk = (const float*)d_in[2];
    const float* Wv = (const float*)d_in[3];
    float* out = (float*)d_out;

    __half *xh,*Wh,*Qh,*Kh,*Kth,*Vth,*Sh,*Ph; float *Zc,*Dn;
    cudaGetSymbolAddress((void**)&xh,  g_xh);
    cudaGetSymbolAddress((void**)&Wh,  g_Wh);
    cudaGetSymbolAddress((void**)&Qh,  g_Q);
    cudaGetSymbolAddress((void**)&Kh,  g_K);
    cudaGetSymbolAddress((void**)&Kth, g_Kt);
    cudaGetSymbolAddress((void**)&Vth, g_Vt);
    cudaGetSymbolAddress((void**)&Sh,  g_S);
    cudaGetSymbolAddress((void**)&Ph,  g_P);
    cudaGetSymbolAddress((void**)&Zc,  g_Zc);
    cudaGetSymbolAddress((void**)&Dn,  g_Dn);

    cudaFuncSetAttribute(proj_kernel,    cudaFuncAttributeMaxDynamicSharedMemorySize, SMEMSZ);
    cudaFuncSetAttribute(dual_gemm,      cudaFuncAttributeMaxDynamicSharedMemorySize, SMEMSZ);
    cudaFuncSetAttribute(fused79_kernel, cudaFuncAttributeMaxDynamicSharedMemorySize, SMEMSZ);

    // 0) convert all inputs to fp16, one launch
    f2h_all_kernel<<<(N8X + 3*N8W + 255)/256, 256>>>(x, Wq, Wk, Wv, xh, Wh);

    // 1) fused projections: Q, K (+Kt), Vt
    proj_kernel<<<dim3(12,128,1),256,SMEMSZ>>>(xh, Wh, Qh, Kh, Kth, Vth);

    // 2) S chunks + masked P, one launch
    dual_gemm<<<dim3(40,NCHUNK,1),256,SMEMSZ>>>(Vth, Kth, Sh, Qh, Kh, Ph);

    // 3) exclusive prefix of S over chunks
    prefix_kernel<<<DD*DD/256, 256>>>(Sh);

    // 4) denominator: chunk sums, then fused cumsum-dot
    kchunksum_kernel<<<NCHUNK*BB*DD/256, 256>>>(Kh, Zc);
    zdot_kernel<<<NCHUNK*BB, 1024>>>(Kh, Qh, Zc, Dn);

    // 5) Y = (Q_c·Sprefix^T + P_c·Vt^T) / denom
    fused79_kernel<<<dim3(4,4,NCHUNK),256,SMEMSZ>>>(Qh, Sh, Ph, Vth, Dn, out);
}

// round 15
// speedup vs baseline: 1.1497x; 1.0221x over previous
#include <cuda_runtime.h>
#include <cuda_fp16.h>
#include <math.h>
#include <stdint.h>

#define TT 4096
#define BB 4
#define DD 1024
#define NTOK (TT*BB)
#define CTOK 512
#define NCHUNK 32

// -------- scratch (fp16 intermediates) --------
__device__ __align__(128) __half g_xh[(size_t)NTOK*DD];
__device__ __align__(128) __half g_Wh[(size_t)3*DD*DD];
__device__ __align__(128) __half g_Q [(size_t)NTOK*DD];
__device__ __align__(128) __half g_K [(size_t)NTOK*DD];
__device__ __align__(128) __half g_Kt[(size_t)DD*NTOK];
__device__ __align__(128) __half g_Vt[(size_t)DD*NTOK];
__device__ __align__(128) __half g_S [(size_t)NCHUNK*DD*DD];
__device__ __align__(128) __half g_P [(size_t)NCHUNK*CTOK*CTOK];
__device__ float g_Zc[(size_t)NCHUNK*BB*DD];
__device__ float g_Dn[NTOK];

#define RSB   80                 // smem row stride bytes (32 halves + pad)
#define ATILE 10240              // 128 rows * 80B
#define BTILE 20480              // 256 rows * 80B
#define STAGE (ATILE + BTILE)    // 30720
#define NSTG  4
#define SMEMSZ (NSTG*STAGE)      // 122880

__device__ __forceinline__ uint32_t smem_u32(const void* p){
    uint32_t a; asm("{ .reg .u64 t; cvta.to.shared.u64 t, %1; cvt.u32.u64 %0, t; }":"=r"(a):"l"(p)); return a;
}
__device__ __forceinline__ void cp16(uint32_t s, const void* g){
    asm volatile("cp.async.cg.shared.global [%0], [%1], 16;" :: "r"(s), "l"(g));
}

// shared staging helper macros (identical math to R8 core)
#define STAGE_DECL                                                            \
    const int a0 = tid*2, a1 = tid*2 + 1;                                     \
    const int b0 = tid*4;                                                     \
    const uint32_t acs0 = sbase + (a0>>2)*RSB + (a0&3)*16;                    \
    const uint32_t acs1 = sbase + (a1>>2)*RSB + (a1&3)*16;                    \
    const uint32_t bcs0 = sbase + ATILE + ((b0  )>>2)*RSB + ((b0  )&3)*16;    \
    const uint32_t bcs1 = sbase + ATILE + ((b0+1)>>2)*RSB + ((b0+1)&3)*16;    \
    const uint32_t bcs2 = sbase + ATILE + ((b0+2)>>2)*RSB + ((b0+2)&3)*16;    \
    const uint32_t bcs3 = sbase + ATILE + ((b0+3)>>2)*RSB + ((b0+3)&3)*16;    \
    const __half *acp0, *acp1, *bcp0, *bcp1, *bcp2, *bcp3;

#define STAGE_SETUP(Abase, lda_, Bbase, ldb_)                                 \
    acp0 = (Abase) + (long)(row0 + (a0>>2))*(lda_) + (a0&3)*8;                \
    acp1 = (Abase) + (long)(row0 + (a1>>2))*(lda_) + (a1&3)*8;                \
    bcp0 = (Bbase) + (long)(col0 + ((b0  )>>2))*(ldb_) + ((b0  )&3)*8;        \
    bcp1 = (Bbase) + (long)(col0 + ((b0+1)>>2))*(ldb_) + ((b0+1)&3)*8;       \
    bcp2 = (Bbase) + (long)(col0 + ((b0+2)>>2))*(ldb_) + ((b0+2)&3)*8;       \
    bcp3 = (Bbase) + (long)(col0 + ((b0+3)>>2))*(ldb_) + ((b0+3)&3)*8;

#define FRAG_DECL                                                             \
    const uint32_t a_lm = (uint32_t)(wm*64*RSB + (lane&15)*RSB + (lane>>4)*16); \
    const uint32_t b_lm = (uint32_t)(ATILE + wn*64*RSB                        \
                        + ((lane&7) + ((lane>>4)&1)*8)*RSB + ((lane>>3)&1)*16);

#define DEF_LOADCP                                                            \
    auto loadcp = [&](int st, int k0){                                        \
        uint32_t so = st*STAGE;                                               \
        cp16(acs0 + so, acp0 + k0);                                           \
        cp16(acs1 + so, acp1 + k0);                                           \
        cp16(bcs0 + so, bcp0 + k0);                                           \
        cp16(bcs1 + so, bcp1 + k0);                                           \
        cp16(bcs2 + so, bcp2 + k0);                                           \
        cp16(bcs3 + so, bcp3 + k0);                                           \
        asm volatile("cp.async.commit_group;" ::: "memory");                  \
    };

#define DEF_MMASTAGE                                                          \
    auto mma_stage = [&](int st){                                             \
        uint32_t base = sbase + st*STAGE;                                     \
        _Pragma("unroll")                                                     \
        for (int kk = 0; kk < 2; kk++){                                       \
            uint32_t af[4][4], bf[8][2];                                      \
            _Pragma("unroll")                                                 \
            for (int mt = 0; mt < 4; mt++){                                   \
                uint32_t ad = base + a_lm + mt*(16*RSB) + kk*32;              \
                asm volatile("ldmatrix.sync.aligned.m8n8.x4.shared.b16 {%0,%1,%2,%3},[%4];" \
                    : "=r"(af[mt][0]),"=r"(af[mt][1]),"=r"(af[mt][2]),"=r"(af[mt][3]) \
                    : "r"(ad));                                               \
            }                                                                 \
            _Pragma("unroll")                                                 \
            for (int p = 0; p < 4; p++){                                      \
                uint32_t bd = base + b_lm + p*(16*RSB) + kk*32;               \
                uint32_t r0,r1,r2,r3;                                         \
                asm volatile("ldmatrix.sync.aligned.m8n8.x4.shared.b16 {%0,%1,%2,%3},[%4];" \
                    : "=r"(r0),"=r"(r1),"=r"(r2),"=r"(r3) : "r"(bd));         \
                bf[2*p][0]=r0; bf[2*p][1]=r1; bf[2*p+1][0]=r2; bf[2*p+1][1]=r3; \
            }                                                                 \
            _Pragma("unroll")                                                 \
            for (int mt = 0; mt < 4; mt++)                                    \
                _Pragma("unroll")                                             \
                for (int nt = 0; nt < 8; nt++)                                \
                    asm volatile(                                             \
                        "mma.sync.aligned.m16n8k16.row.col.f32.f16.f16.f32 "  \
                        "{%0,%1,%2,%3},{%4,%5,%6,%7},{%8,%9},{%0,%1,%2,%3};"  \
                        : "+f"(acc[mt][nt][0]),"+f"(acc[mt][nt][1]),          \
                          "+f"(acc[mt][nt][2]),"+f"(acc[mt][nt][3])           \
                        : "r"(af[mt][0]),"r"(af[mt][1]),"r"(af[mt][2]),"r"(af[mt][3]), \
                          "r"(bf[nt][0]),"r"(bf[nt][1]));                     \
        }                                                                     \
    };

#define DEF_PIPELINE                                                          \
    auto run_pipeline = [&](int n){                                           \
        loadcp(0, 0);                                                         \
        loadcp(1, 32);                                                        \
        loadcp(2, 64);                                                        \
        for (int s = 0; s < n; s++){                                          \
            if (s < n-2)       asm volatile("cp.async.wait_group 2;" ::: "memory"); \
            else if (s == n-2) asm volatile("cp.async.wait_group 1;" ::: "memory"); \
            else               asm volatile("cp.async.wait_group 0;" ::: "memory"); \
            __syncthreads();                                                  \
            if (s + 3 < n) loadcp((s+3)&3, (s+3)*32);                         \
            mma_stage(s & 3);                                                 \
        }                                                                     \
    };

// =====================================================================
// dual GEMM: one launch for step 4 (S = Vt·Kt^T) and step 8 (P = mask(Q·K^T))
// grid (40, NCHUNK): x<32 -> S tile (4x,8y); x>=32 -> P tile (2x,4y)
// =====================================================================
__global__ void __launch_bounds__(256, 1) dual_gemm(
    const __half* __restrict__ Vth, const __half* __restrict__ Kth,
    __half* __restrict__ Sh,
    const __half* __restrict__ Qh, const __half* __restrict__ Kh,
    __half* __restrict__ Ph)
{
    extern __shared__ char smem[];
    const uint32_t sbase = smem_u32(smem);
    const int tid  = threadIdx.x;
    const int lane = tid & 31;
    const int warp = tid >> 5;
    const int wm = warp >> 2, wn = warp & 3;
    const int gid = lane >> 2, tig = lane & 3;
    const int chunk = blockIdx.y;
    const int xid = blockIdx.x;
    const bool isP = (xid >= 32);

    const __half *Ah, *Bh; __half* Chh;
    int lda, ldb, ldc, Kdim, row0, col0;
    if (!isP){
        int xx = xid & 3, yy = xid >> 2;
        Ah = Vth + (long)chunk*CTOK;  lda = NTOK;
        Bh = Kth + (long)chunk*CTOK;  ldb = NTOK;
        Chh = Sh + (size_t)chunk*DD*DD; ldc = DD;
        Kdim = CTOK; row0 = yy*128; col0 = xx*256;
    } else {
        int t = xid - 32;
        int xx = t & 1, yy = t >> 1;
        Ah = Qh + (long)chunk*CTOK*DD; lda = DD;
        Bh = Kh + (long)chunk*CTOK*DD; ldb = DD;
        Chh = Ph + (size_t)chunk*CTOK*CTOK; ldc = CTOK;
        Kdim = DD; row0 = yy*128; col0 = xx*256;
    }

    // fully-masked P tile: write zeros and exit
    if (isP && ((col0 >> 2) > ((row0 + 127) >> 2))){
        #pragma unroll
        for (int it = 0; it < 16; it++){
            int task = it*256 + tid;
            int r = task >> 5, ch = task & 31;
            uint4 z = make_uint4(0,0,0,0);
            *(uint4*)&Chh[(long)(row0 + r)*ldc + col0 + ch*8] = z;
        }
        return;
    }

    float acc[4][8][4] = {};
    FRAG_DECL
    STAGE_DECL
    STAGE_SETUP(Ah, lda, Bh, ldb)
    DEF_LOADCP
    DEF_MMASTAGE
    DEF_PIPELINE

    run_pipeline(Kdim >> 5);

    #pragma unroll
    for (int mt = 0; mt < 4; mt++){
        int r0 = row0 + wm*64 + mt*16 + gid;
        int r1 = r0 + 8;
        #pragma unroll
        for (int nt = 0; nt < 8; nt++){
            int c0 = col0 + wn*64 + nt*8 + 2*tig;
            float v[4];
            #pragma unroll
            for (int e = 0; e < 4; e++){
                float f = acc[mt][nt][e];
                if (isP){
                    int r = (e < 2) ? r0 : r1;
                    int c = c0 + (e & 1);
                    if ((c >> 2) > (r >> 2)) f = 0.0f;
                }
                v[e] = f;
            }
            *(__half2*)(Chh + (long)r0*ldc + c0) = __floats2half2_rn(v[0], v[1]);
            *(__half2*)(Chh + (long)r1*ldc + c0) = __floats2half2_rn(v[2], v[3]);
        }
    }
}

// =====================================================================
// fused Q/K/V projection: grid (12,128)
// =====================================================================
__global__ void __launch_bounds__(256, 1) proj_kernel(
    const __half* __restrict__ xh, const __half* __restrict__ Wall,
    __half* __restrict__ Qh, __half* __restrict__ Kh,
    __half* __restrict__ Kth, __half* __restrict__ Vth)
{
    extern __shared__ char smem[];
    const uint32_t sbase = smem_u32(smem);
    const int tid  = threadIdx.x;
    const int lane = tid & 31;
    const int warp = tid >> 5;
    const int wm = warp >> 2, wn = warp & 3;
    const int gid = lane >> 2, tig = lane & 3;
    const int m    = blockIdx.x >> 2;            // 0=Q 1=K 2=V
    const int col0 = (blockIdx.x & 3) * 256;
    const int row0 = blockIdx.y * 128;

    const __half* Ah = xh;
    const __half* Bh = Wall + (size_t)m*DD*DD;

    float acc[4][8][4] = {};
    FRAG_DECL
    STAGE_DECL
    STAGE_SETUP(Ah, DD, Bh, DD)
    DEF_LOADCP
    DEF_MMASTAGE
    DEF_PIPELINE

    run_pipeline(DD >> 5);

    const bool act = (m < 2);
    __half* Cn = (m == 0) ? Qh : Kh;
    __half* Ct = (m == 1) ? Kth : Vth;

    #pragma unroll
    for (int mt = 0; mt < 4; mt++){
        int r0 = row0 + wm*64 + mt*16 + gid;
        int r1 = r0 + 8;
        #pragma unroll
        for (int nt = 0; nt < 8; nt++){
            int c0 = col0 + wn*64 + nt*8 + 2*tig;
            float v[4];
            #pragma unroll
            for (int e = 0; e < 4; e++){
                float f = acc[mt][nt][e];
                if (act) f = (f > 0.0f) ? (f + 1.0f) : expf(f);
                v[e] = f;
            }
            if (m <= 1){
                *(__half2*)(Cn + (long)r0*DD + c0) = __floats2half2_rn(v[0], v[1]);
                *(__half2*)(Cn + (long)r1*DD + c0) = __floats2half2_rn(v[2], v[3]);
            }
            if (m >= 1){
                Ct[(long)(c0  )*NTOK + r0] = __float2half(v[0]);
                Ct[(long)(c0+1)*NTOK + r0] = __float2half(v[1]);
                Ct[(long)(c0  )*NTOK + r1] = __float2half(v[2]);
                Ct[(long)(c0+1)*NTOK + r1] = __float2half(v[3]);
            }
        }
    }
}

// =====================================================================
// fused steps 7+9: Y = (Q_c·Sprefix_c^T + P_c·Vt_c^T) / denom  (fp32 out)
// =====================================================================
__global__ void __launch_bounds__(256, 1) fused79_kernel(
    const __half* __restrict__ Qh, const __half* __restrict__ Sh,
    const __half* __restrict__ Ph, const __half* __restrict__ Vth,
    const float* __restrict__ Dn, float* __restrict__ out)
{
    extern __shared__ char smem[];
    const uint32_t sbase = smem_u32(smem);
    const int tid  = threadIdx.x;
    const int lane = tid & 31;
    const int warp = tid >> 5;
    const int wm = warp >> 2, wn = warp & 3;
    const int gid = lane >> 2, tig = lane & 3;
    const int bz = blockIdx.z;
    const int row0 = blockIdx.y * 128;
    const int col0 = blockIdx.x * 256;

    float acc[4][8][4] = {};
    FRAG_DECL
    STAGE_DECL
    DEF_LOADCP
    DEF_MMASTAGE
    DEF_PIPELINE

    STAGE_SETUP(Qh + (long)bz*CTOK*DD, DD, Sh + (size_t)bz*DD*DD, DD)
    run_pipeline(DD >> 5);

    STAGE_SETUP(Ph + (size_t)bz*CTOK*CTOK, CTOK, Vth + (long)bz*CTOK, NTOK)
    run_pipeline(CTOK >> 5);

    float* Cf = out + (long)bz*CTOK*DD;
    #pragma unroll
    for (int mt = 0; mt < 4; mt++){
        int r0 = row0 + wm*64 + mt*16 + gid;
        int r1 = r0 + 8;
        float dn0 = Dn[(long)bz*CTOK + r0];
        float dn1 = Dn[(long)bz*CTOK + r1];
        #pragma unroll
        for (int nt = 0; nt < 8; nt++){
            int c0 = col0 + wn*64 + nt*8 + 2*tig;
            float2 p0 = make_float2(acc[mt][nt][0]/dn0, acc[mt][nt][1]/dn0);
            float2 p1 = make_float2(acc[mt][nt][2]/dn1, acc[mt][nt][3]/dn1);
            *(float2*)(Cf + (long)r0*DD + c0) = p0;
            *(float2*)(Cf + (long)r1*DD + c0) = p1;
        }
    }
}

// -------- single-launch fp32 -> fp16 conversion (x | Wq | Wk | Wv) --------
#define N8X (NTOK*DD/8)
#define N8W (DD*DD/8)
__global__ void f2h_all_kernel(const float* __restrict__ x,
                               const float* __restrict__ Wq,
                               const float* __restrict__ Wk,
                               const float* __restrict__ Wv,
                               __half* __restrict__ xh, __half* __restrict__ Wh)
{
    int i = blockIdx.x * blockDim.x + threadIdx.x;
    const float* src; __half* dst; int l;
    if (i < N8X)            { src = x;  dst = xh;            l = i; }
    else if (i < N8X+N8W)   { src = Wq; dst = Wh;            l = i - N8X; }
    else if (i < N8X+2*N8W) { src = Wk; dst = Wh + (size_t)DD*DD;   l = i - N8X - N8W; }
    else if (i < N8X+3*N8W) { src = Wv; dst = Wh + (size_t)2*N8W*8; l = i - N8X - 2*N8W; }
    else return;
    float4 a = ((const float4*)src)[2*l];
    float4 b = ((const float4*)src)[2*l+1];
    __half2 h[4] = { __floats2half2_rn(a.x,a.y), __floats2half2_rn(a.z,a.w),
                     __floats2half2_rn(b.x,b.y), __floats2half2_rn(b.z,b.w) };
    ((uint4*)dst)[l] = *(uint4*)h;
}

// -------- vectorized exclusive prefix of S over chunks (uint4, prefetch) --------
// 1M elements / 8 per thread = 131072 threads; grid 512 x 256
__global__ void prefix_kernel(__half* __restrict__ S)
{
    size_t base = ((size_t)blockIdx.x * blockDim.x + threadIdx.x) * 8;
    float acc[8] = {0,0,0,0,0,0,0,0};
    uint4 cur = *(const uint4*)&S[base];
    #pragma unroll 4
    for (int c = 0; c < NCHUNK; c++){
        size_t off = (size_t)c*DD*DD + base;
        uint4 nxt;
        if (c + 1 < NCHUNK) nxt = *(const uint4*)&S[off + (size_t)DD*DD];
        __half2* hp = (__half2*)&cur;
        uint4 outv; __half2* op = (__half2*)&outv;
        #pragma unroll
        for (int i = 0; i < 4; i++){
            float2 f = __half22float2(hp[i]);
            op[i] = __floats2half2_rn(acc[2*i], acc[2*i+1]);
            acc[2*i]   += f.x;
            acc[2*i+1] += f.y;
        }
        *(uint4*)&S[off] = outv;
        cur = nxt;
    }
}

// -------- aux kernels --------
__global__ void kchunksum_kernel(const __half* __restrict__ Kp, float* __restrict__ Zc)
{
    int id = blockIdx.x * blockDim.x + threadIdx.x;   // < NCHUNK*4096
    int c = id >> 12, bd = id & 4095;
    const __half* p = Kp + (long)c*128*4096 + bd;
    float s = 0.0f;
    #pragma unroll 8
    for (int t = 0; t < 128; t++) s += __half2float(p[(long)t*4096]);
    Zc[id] = s;
}
// fused cumsum+dot: Dn[token] = Q[token] . zcum[token]
__global__ void __launch_bounds__(1024) zdot_kernel(
    const __half* __restrict__ Kp, const __half* __restrict__ Qp,
    const float* __restrict__ Zc, float* __restrict__ Dn)
{
    __shared__ float part[128][33];
    const int c = blockIdx.x >> 2;
    const int b = blockIdx.x & 3;
    const int d = threadIdx.x;
    const int lane = d & 31, w = d >> 5;

    float acc = 0.0f;
    for (int cp = 0; cp < c; cp++) acc += Zc[cp*4096 + b*1024 + d];

    const long base = ((long)(c*128)*4 + b)*1024 + d;
    #pragma unroll 4
    for (int t = 0; t < 128; t++){
        long off = base + (long)t*4096;
        acc += __half2float(Kp[off]);
        float s = __half2float(Qp[off]) * acc;
        #pragma unroll
        for (int o = 16; o; o >>= 1) s += __shfl_down_sync(0xffffffffu, s, o);
        if (lane == 0) part[t][w] = s;
    }
    __syncthreads();
    if (d < 128){
        float s = 0.0f;
        #pragma unroll
        for (int i = 0; i < 32; i++) s += part[d][i];
        Dn[((long)(c*128 + d))*4 + b] = s;
    }
}

extern "C" void kernel_launch(void* const* d_in, const int* in_sizes, int n_in,
                              void* d_out, int out_size)
{
    const float* x  = (const float*)d_in[0];
    const float* Wq = (const float*)d_in[1];
    const float* Wk = (const float*)d_in[2];
    const float* Wv = (const float*)d_in[3];
    float* out = (float*)d_out;

    __half *xh,*Wh,*Qh,*Kh,*Kth,*Vth,*Sh,*Ph; float *Zc,*Dn;
    cudaGetSymbolAddress((void**)&xh,  g_xh);
    cudaGetSymbolAddress((void**)&Wh,  g_Wh);
    cudaGetSymbolAddress((void**)&Qh,  g_Q);
    cudaGetSymbolAddress((void**)&Kh,  g_K);
    cudaGetSymbolAddress((void**)&Kth, g_Kt);
    cudaGetSymbolAddress((void**)&Vth, g_Vt);
    cudaGetSymbolAddress((void**)&Sh,  g_S);
    cudaGetSymbolAddress((void**)&Ph,  g_P);
    cudaGetSymbolAddress((void**)&Zc,  g_Zc);
    cudaGetSymbolAddress((void**)&Dn,  g_Dn);

    cudaFuncSetAttribute(proj_kernel,    cudaFuncAttributeMaxDynamicSharedMemorySize, SMEMSZ);
    cudaFuncSetAttribute(dual_gemm,      cudaFuncAttributeMaxDynamicSharedMemorySize, SMEMSZ);
    cudaFuncSetAttribute(fused79_kernel, cudaFuncAttributeMaxDynamicSharedMemorySize, SMEMSZ);

    // 0) convert all inputs to fp16, one launch
    f2h_all_kernel<<<(N8X + 3*N8W + 255)/256, 256>>>(x, Wq, Wk, Wv, xh, Wh);

    // 1) fused projections: Q, K (+Kt), Vt
    proj_kernel<<<dim3(12,128,1),256,SMEMSZ>>>(xh, Wh, Qh, Kh, Kth, Vth);

    // 2) S chunks + masked P, one launch
    dual_gemm<<<dim3(40,NCHUNK,1),256,SMEMSZ>>>(Vth, Kth, Sh, Qh, Kh, Ph);

    // 3) exclusive prefix of S over chunks (vectorized)
    prefix_kernel<<<512, 256>>>(Sh);

    // 4) denominator: chunk sums, then fused cumsum-dot
    kchunksum_kernel<<<NCHUNK*BB*DD/256, 256>>>(Kh, Zc);
    zdot_kernel<<<NCHUNK*BB, 1024>>>(Kh, Qh, Zc, Dn);

    // 5) Y = (Q_c·Sprefix^T + P_c·Vt^T) / denom
    fused79_kernel<<<dim3(4,4,NCHUNK),256,SMEMSZ>>>(Qh, Sh, Ph, Vth, Dn, out);
}

// round 16
// speedup vs baseline: 1.2055x; 1.0486x over previous
#include <cuda_runtime.h>
#include <cuda_fp16.h>
#include <math.h>
#include <stdint.h>

#define TT 4096
#define BB 4
#define DD 1024
#define NTOK (TT*BB)
#define CTOK 512
#define NCHUNK 32

// -------- scratch (fp16 intermediates) --------
__device__ __align__(128) __half g_xh[(size_t)NTOK*DD];
__device__ __align__(128) __half g_Wh[(size_t)3*DD*DD];
__device__ __align__(128) __half g_Q [(size_t)NTOK*DD];
__device__ __align__(128) __half g_K [(size_t)NTOK*DD];
__device__ __align__(128) __half g_Kt[(size_t)DD*NTOK];
__device__ __align__(128) __half g_Vt[(size_t)DD*NTOK];
__device__ __align__(128) __half g_S [(size_t)NCHUNK*DD*DD];
__device__ __align__(128) __half g_P [(size_t)NCHUNK*CTOK*CTOK];
__device__ float g_Zc[(size_t)NCHUNK*BB*DD];
__device__ float g_Dn[NTOK];

#define RSB   80                 // smem row stride bytes (32 halves + pad)
#define ATILE 10240              // 128 rows * 80B
#define BTILE 20480              // 256 rows * 80B
#define STAGE (ATILE + BTILE)    // 30720
#define NSTG  4
#define SMEMSZ (NSTG*STAGE)      // 122880

__device__ __forceinline__ uint32_t smem_u32(const void* p){
    uint32_t a; asm("{ .reg .u64 t; cvta.to.shared.u64 t, %1; cvt.u32.u64 %0, t; }":"=r"(a):"l"(p)); return a;
}
__device__ __forceinline__ void cp16(uint32_t s, const void* g){
    asm volatile("cp.async.cg.shared.global [%0], [%1], 16;" :: "r"(s), "l"(g));
}

// shared staging helper macros (identical math to R8 core)
#define STAGE_DECL                                                            \
    const int a0 = tid*2, a1 = tid*2 + 1;                                     \
    const int b0 = tid*4;                                                     \
    const uint32_t acs0 = sbase + (a0>>2)*RSB + (a0&3)*16;                    \
    const uint32_t acs1 = sbase + (a1>>2)*RSB + (a1&3)*16;                    \
    const uint32_t bcs0 = sbase + ATILE + ((b0  )>>2)*RSB + ((b0  )&3)*16;    \
    const uint32_t bcs1 = sbase + ATILE + ((b0+1)>>2)*RSB + ((b0+1)&3)*16;    \
    const uint32_t bcs2 = sbase + ATILE + ((b0+2)>>2)*RSB + ((b0+2)&3)*16;    \
    const uint32_t bcs3 = sbase + ATILE + ((b0+3)>>2)*RSB + ((b0+3)&3)*16;    \
    const __half *acp0, *acp1, *bcp0, *bcp1, *bcp2, *bcp3;

#define STAGE_SETUP(Abase, lda_, Bbase, ldb_)                                 \
    acp0 = (Abase) + (long)(row0 + (a0>>2))*(lda_) + (a0&3)*8;                \
    acp1 = (Abase) + (long)(row0 + (a1>>2))*(lda_) + (a1&3)*8;                \
    bcp0 = (Bbase) + (long)(col0 + ((b0  )>>2))*(ldb_) + ((b0  )&3)*8;        \
    bcp1 = (Bbase) + (long)(col0 + ((b0+1)>>2))*(ldb_) + ((b0+1)&3)*8;       \
    bcp2 = (Bbase) + (long)(col0 + ((b0+2)>>2))*(ldb_) + ((b0+2)&3)*8;       \
    bcp3 = (Bbase) + (long)(col0 + ((b0+3)>>2))*(ldb_) + ((b0+3)&3)*8;

#define FRAG_DECL                                                             \
    const uint32_t a_lm = (uint32_t)(wm*64*RSB + (lane&15)*RSB + (lane>>4)*16); \
    const uint32_t b_lm = (uint32_t)(ATILE + wn*64*RSB                        \
                        + ((lane&7) + ((lane>>4)&1)*8)*RSB + ((lane>>3)&1)*16);

#define DEF_LOADCP                                                            \
    auto loadcp = [&](int st, int k0){                                        \
        uint32_t so = st*STAGE;                                               \
        cp16(acs0 + so, acp0 + k0);                                           \
        cp16(acs1 + so, acp1 + k0);                                           \
        cp16(bcs0 + so, bcp0 + k0);                                           \
        cp16(bcs1 + so, bcp1 + k0);                                           \
        cp16(bcs2 + so, bcp2 + k0);                                           \
        cp16(bcs3 + so, bcp3 + k0);                                           \
        asm volatile("cp.async.commit_group;" ::: "memory");                  \
    };

#define DEF_MMASTAGE                                                          \
    auto mma_stage = [&](int st){                                             \
        uint32_t base = sbase + st*STAGE;                                     \
        _Pragma("unroll")                                                     \
        for (int kk = 0; kk < 2; kk++){                                       \
            uint32_t af[4][4], bf[8][2];                                      \
            _Pragma("unroll")                                                 \
            for (int mt = 0; mt < 4; mt++){                                   \
                uint32_t ad = base + a_lm + mt*(16*RSB) + kk*32;              \
                asm volatile("ldmatrix.sync.aligned.m8n8.x4.shared.b16 {%0,%1,%2,%3},[%4];" \
                    : "=r"(af[mt][0]),"=r"(af[mt][1]),"=r"(af[mt][2]),"=r"(af[mt][3]) \
                    : "r"(ad));                                               \
            }                                                                 \
            _Pragma("unroll")                                                 \
            for (int p = 0; p < 4; p++){                                      \
                uint32_t bd = base + b_lm + p*(16*RSB) + kk*32;               \
                uint32_t r0,r1,r2,r3;                                         \
                asm volatile("ldmatrix.sync.aligned.m8n8.x4.shared.b16 {%0,%1,%2,%3},[%4];" \
                    : "=r"(r0),"=r"(r1),"=r"(r2),"=r"(r3) : "r"(bd));         \
                bf[2*p][0]=r0; bf[2*p][1]=r1; bf[2*p+1][0]=r2; bf[2*p+1][1]=r3; \
            }                                                                 \
            _Pragma("unroll")                                                 \
            for (int mt = 0; mt < 4; mt++)                                    \
                _Pragma("unroll")                                             \
                for (int nt = 0; nt < 8; nt++)                                \
                    asm volatile(                                             \
                        "mma.sync.aligned.m16n8k16.row.col.f32.f16.f16.f32 "  \
                        "{%0,%1,%2,%3},{%4,%5,%6,%7},{%8,%9},{%0,%1,%2,%3};"  \
                        : "+f"(acc[mt][nt][0]),"+f"(acc[mt][nt][1]),          \
                          "+f"(acc[mt][nt][2]),"+f"(acc[mt][nt][3])           \
                        : "r"(af[mt][0]),"r"(af[mt][1]),"r"(af[mt][2]),"r"(af[mt][3]), \
                          "r"(bf[nt][0]),"r"(bf[nt][1]));                     \
        }                                                                     \
    };

#define DEF_PIPELINE                                                          \
    auto run_pipeline = [&](int n){                                           \
        loadcp(0, 0);                                                         \
        loadcp(1, 32);                                                        \
        loadcp(2, 64);                                                        \
        for (int s = 0; s < n; s++){                                          \
            if (s < n-2)       asm volatile("cp.async.wait_group 2;" ::: "memory"); \
            else if (s == n-2) asm volatile("cp.async.wait_group 1;" ::: "memory"); \
            else               asm volatile("cp.async.wait_group 0;" ::: "memory"); \
            __syncthreads();                                                  \
            if (s + 3 < n) loadcp((s+3)&3, (s+3)*32);                         \
            mma_stage(s & 3);                                                 \
        }                                                                     \
    };

// =====================================================================
// dual GEMM: one launch for step 4 (S = Vt·Kt^T) and step 8 (P = mask(Q·K^T))
// =====================================================================
__global__ void __launch_bounds__(256, 1) dual_gemm(
    const __half* __restrict__ Vth, const __half* __restrict__ Kth,
    __half* __restrict__ Sh,
    const __half* __restrict__ Qh, const __half* __restrict__ Kh,
    __half* __restrict__ Ph)
{
    extern __shared__ char smem[];
    const uint32_t sbase = smem_u32(smem);
    const int tid  = threadIdx.x;
    const int lane = tid & 31;
    const int warp = tid >> 5;
    const int wm = warp >> 2, wn = warp & 3;
    const int gid = lane >> 2, tig = lane & 3;
    const int chunk = blockIdx.y;
    const int xid = blockIdx.x;
    const bool isP = (xid >= 32);

    const __half *Ah, *Bh; __half* Chh;
    int lda, ldb, ldc, Kdim, row0, col0;
    if (!isP){
        int xx = xid & 3, yy = xid >> 2;
        Ah = Vth + (long)chunk*CTOK;  lda = NTOK;
        Bh = Kth + (long)chunk*CTOK;  ldb = NTOK;
        Chh = Sh + (size_t)chunk*DD*DD; ldc = DD;
        Kdim = CTOK; row0 = yy*128; col0 = xx*256;
    } else {
        int t = xid - 32;
        int xx = t & 1, yy = t >> 1;
        Ah = Qh + (long)chunk*CTOK*DD; lda = DD;
        Bh = Kh + (long)chunk*CTOK*DD; ldb = DD;
        Chh = Ph + (size_t)chunk*CTOK*CTOK; ldc = CTOK;
        Kdim = DD; row0 = yy*128; col0 = xx*256;
    }

    if (isP && ((col0 >> 2) > ((row0 + 127) >> 2))){
        #pragma unroll
        for (int it = 0; it < 16; it++){
            int task = it*256 + tid;
            int r = task >> 5, ch = task & 31;
            uint4 z = make_uint4(0,0,0,0);
            *(uint4*)&Chh[(long)(row0 + r)*ldc + col0 + ch*8] = z;
        }
        return;
    }

    float acc[4][8][4] = {};
    FRAG_DECL
    STAGE_DECL
    STAGE_SETUP(Ah, lda, Bh, ldb)
    DEF_LOADCP
    DEF_MMASTAGE
    DEF_PIPELINE

    run_pipeline(Kdim >> 5);

    #pragma unroll
    for (int mt = 0; mt < 4; mt++){
        int r0 = row0 + wm*64 + mt*16 + gid;
        int r1 = r0 + 8;
        #pragma unroll
        for (int nt = 0; nt < 8; nt++){
            int c0 = col0 + wn*64 + nt*8 + 2*tig;
            float v[4];
            #pragma unroll
            for (int e = 0; e < 4; e++){
                float f = acc[mt][nt][e];
                if (isP){
                    int r = (e < 2) ? r0 : r1;
                    int c = c0 + (e & 1);
                    if ((c >> 2) > (r >> 2)) f = 0.0f;
                }
                v[e] = f;
            }
            *(__half2*)(Chh + (long)r0*ldc + c0) = __floats2half2_rn(v[0], v[1]);
            *(__half2*)(Chh + (long)r1*ldc + c0) = __floats2half2_rn(v[2], v[3]);
        }
    }
}

// =====================================================================
// fused Q/K/V projection: grid (12,128)
// =====================================================================
__global__ void __launch_bounds__(256, 1) proj_kernel(
    const __half* __restrict__ xh, const __half* __restrict__ Wall,
    __half* __restrict__ Qh, __half* __restrict__ Kh,
    __half* __restrict__ Kth, __half* __restrict__ Vth)
{
    extern __shared__ char smem[];
    const uint32_t sbase = smem_u32(smem);
    const int tid  = threadIdx.x;
    const int lane = tid & 31;
    const int warp = tid >> 5;
    const int wm = warp >> 2, wn = warp & 3;
    const int gid = lane >> 2, tig = lane & 3;
    const int m    = blockIdx.x >> 2;            // 0=Q 1=K 2=V
    const int col0 = (blockIdx.x & 3) * 256;
    const int row0 = blockIdx.y * 128;

    const __half* Ah = xh;
    const __half* Bh = Wall + (size_t)m*DD*DD;

    float acc[4][8][4] = {};
    FRAG_DECL
    STAGE_DECL
    STAGE_SETUP(Ah, DD, Bh, DD)
    DEF_LOADCP
    DEF_MMASTAGE
    DEF_PIPELINE

    run_pipeline(DD >> 5);

    const bool act = (m < 2);
    __half* Cn = (m == 0) ? Qh : Kh;
    __half* Ct = (m == 1) ? Kth : Vth;

    #pragma unroll
    for (int mt = 0; mt < 4; mt++){
        int r0 = row0 + wm*64 + mt*16 + gid;
        int r1 = r0 + 8;
        #pragma unroll
        for (int nt = 0; nt < 8; nt++){
            int c0 = col0 + wn*64 + nt*8 + 2*tig;
            float v[4];
            #pragma unroll
            for (int e = 0; e < 4; e++){
                float f = acc[mt][nt][e];
                if (act) f = (f > 0.0f) ? (f + 1.0f) : expf(f);
                v[e] = f;
            }
            if (m <= 1){
                *(__half2*)(Cn + (long)r0*DD + c0) = __floats2half2_rn(v[0], v[1]);
                *(__half2*)(Cn + (long)r1*DD + c0) = __floats2half2_rn(v[2], v[3]);
            }
            if (m >= 1){
                Ct[(long)(c0  )*NTOK + r0] = __float2half(v[0]);
                Ct[(long)(c0+1)*NTOK + r0] = __float2half(v[1]);
                Ct[(long)(c0  )*NTOK + r1] = __float2half(v[2]);
                Ct[(long)(c0+1)*NTOK + r1] = __float2half(v[3]);
            }
        }
    }
}

// =====================================================================
// fused steps 7+9: Y = (Q_c·Sprefix_c^T + P_c·Vt_c^T) / denom  (fp32 out)
// =====================================================================
__global__ void __launch_bounds__(256, 1) fused79_kernel(
    const __half* __restrict__ Qh, const __half* __restrict__ Sh,
    const __half* __restrict__ Ph, const __half* __restrict__ Vth,
    const float* __restrict__ Dn, float* __restrict__ out)
{
    extern __shared__ char smem[];
    const uint32_t sbase = smem_u32(smem);
    const int tid  = threadIdx.x;
    const int lane = tid & 31;
    const int warp = tid >> 5;
    const int wm = warp >> 2, wn = warp & 3;
    const int gid = lane >> 2, tig = lane & 3;
    const int bz = blockIdx.z;
    const int row0 = blockIdx.y * 128;
    const int col0 = blockIdx.x * 256;

    float acc[4][8][4] = {};
    FRAG_DECL
    STAGE_DECL
    DEF_LOADCP
    DEF_MMASTAGE
    DEF_PIPELINE

    STAGE_SETUP(Qh + (long)bz*CTOK*DD, DD, Sh + (size_t)bz*DD*DD, DD)
    run_pipeline(DD >> 5);

    STAGE_SETUP(Ph + (size_t)bz*CTOK*CTOK, CTOK, Vth + (long)bz*CTOK, NTOK)
    run_pipeline(CTOK >> 5);

    float* Cf = out + (long)bz*CTOK*DD;
    #pragma unroll
    for (int mt = 0; mt < 4; mt++){
        int r0 = row0 + wm*64 + mt*16 + gid;
        int r1 = r0 + 8;
        float dn0 = Dn[(long)bz*CTOK + r0];
        float dn1 = Dn[(long)bz*CTOK + r1];
        #pragma unroll
        for (int nt = 0; nt < 8; nt++){
            int c0 = col0 + wn*64 + nt*8 + 2*tig;
            float2 p0 = make_float2(acc[mt][nt][0]/dn0, acc[mt][nt][1]/dn0);
            float2 p1 = make_float2(acc[mt][nt][2]/dn1, acc[mt][nt][3]/dn1);
            *(float2*)(Cf + (long)r0*DD + c0) = p0;
            *(float2*)(Cf + (long)r1*DD + c0) = p1;
        }
    }
}

// -------- single-launch fp32 -> fp16 conversion (x | Wq | Wk | Wv) --------
#define N8X (NTOK*DD/8)
#define N8W (DD*DD/8)
__global__ void f2h_all_kernel(const float* __restrict__ x,
                               const float* __restrict__ Wq,
                               const float* __restrict__ Wk,
                               const float* __restrict__ Wv,
                               __half* __restrict__ xh, __half* __restrict__ Wh)
{
    int i = blockIdx.x * blockDim.x + threadIdx.x;
    const float* src; __half* dst; int l;
    if (i < N8X)            { src = x;  dst = xh;            l = i; }
    else if (i < N8X+N8W)   { src = Wq; dst = Wh;            l = i - N8X; }
    else if (i < N8X+2*N8W) { src = Wk; dst = Wh + (size_t)DD*DD;   l = i - N8X - N8W; }
    else if (i < N8X+3*N8W) { src = Wv; dst = Wh + (size_t)2*DD*DD; l = i - N8X - 2*N8W; }
    else return;
    float4 a = ((const float4*)src)[2*l];
    float4 b = ((const float4*)src)[2*l+1];
    __half2 h[4] = { __floats2half2_rn(a.x,a.y), __floats2half2_rn(a.z,a.w),
                     __floats2half2_rn(b.x,b.y), __floats2half2_rn(b.z,b.w) };
    ((uint4*)dst)[l] = *(uint4*)h;
}

// -------- exclusive prefix of S over chunks: v3 (uint2/thread, ring prefetch) --------
// 1M elements / 4 per thread = 262144 threads; grid 1024 x 256
__global__ void prefix_kernel(__half* __restrict__ S)
{
    size_t base = ((size_t)blockIdx.x * blockDim.x + threadIdx.x) * 4;
    float acc[4] = {0,0,0,0};
    uint2 ring[2];
    ring[0] = *(const uint2*)&S[base];
    ring[1] = *(const uint2*)&S[(size_t)DD*DD + base];
    #pragma unroll 4
    for (int c = 0; c < NCHUNK; c++){
        size_t off = (size_t)c*DD*DD + base;
        uint2 cur = ring[c & 1];
        if (c + 2 < NCHUNK)
            ring[c & 1] = *(const uint2*)&S[off + (size_t)2*DD*DD];
        __half2* hp = (__half2*)&cur;
        uint2 outv; __half2* op = (__half2*)&outv;
        #pragma unroll
        for (int i = 0; i < 2; i++){
            float2 f = __half22float2(hp[i]);
            op[i] = __floats2half2_rn(acc[2*i], acc[2*i+1]);
            acc[2*i]   += f.x;
            acc[2*i+1] += f.y;
        }
        *(uint2*)&S[off] = outv;
    }
}

// -------- aux kernels --------
__global__ void kchunksum_kernel(const __half* __restrict__ Kp, float* __restrict__ Zc)
{
    int id = blockIdx.x * blockDim.x + threadIdx.x;   // < NCHUNK*4096
    int c = id >> 12, bd = id & 4095;
    const __half* p = Kp + (long)c*128*4096 + bd;
    float s = 0.0f;
    #pragma unroll 8
    for (int t = 0; t < 128; t++) s += __half2float(p[(long)t*4096]);
    Zc[id] = s;
}
// fused cumsum+dot: Dn[token] = Q[token] . zcum[token]
__global__ void __launch_bounds__(1024) zdot_kernel(
    const __half* __restrict__ Kp, const __half* __restrict__ Qp,
    const float* __restrict__ Zc, float* __restrict__ Dn)
{
    __shared__ float part[128][33];
    const int c = blockIdx.x >> 2;
    const int b = blockIdx.x & 3;
    const int d = threadIdx.x;
    const int lane = d & 31, w = d >> 5;

    float acc = 0.0f;
    for (int cp = 0; cp < c; cp++) acc += Zc[cp*4096 + b*1024 + d];

    const long base = ((long)(c*128)*4 + b)*1024 + d;
    #pragma unroll 4
    for (int t = 0; t < 128; t++){
        long off = base + (long)t*4096;
        acc += __half2float(Kp[off]);
        float s = __half2float(Qp[off]) * acc;
        #pragma unroll
        for (int o = 16; o; o >>= 1) s += __shfl_down_sync(0xffffffffu, s, o);
        if (lane == 0) part[t][w] = s;
    }
    __syncthreads();
    if (d < 128){
        float s = 0.0f;
        #pragma unroll
        for (int i = 0; i < 32; i++) s += part[d][i];
        Dn[((long)(c*128 + d))*4 + b] = s;
    }
}

extern "C" void kernel_launch(void* const* d_in, const int* in_sizes, int n_in,
                              void* d_out, int out_size)
{
    const float* x  = (const float*)d_in[0];
    const float* Wq = (const float*)d_in[1];
    const float* Wk = (const float*)d_in[2];
    const float* Wv = (const float*)d_in[3];
    float* out = (float*)d_out;

    __half *xh,*Wh,*Qh,*Kh,*Kth,*Vth,*Sh,*Ph; float *Zc,*Dn;
    cudaGetSymbolAddress((void**)&xh,  g_xh);
    cudaGetSymbolAddress((void**)&Wh,  g_Wh);
    cudaGetSymbolAddress((void**)&Qh,  g_Q);
    cudaGetSymbolAddress((void**)&Kh,  g_K);
    cudaGetSymbolAddress((void**)&Kth, g_Kt);
    cudaGetSymbolAddress((void**)&Vth, g_Vt);
    cudaGetSymbolAddress((void**)&Sh,  g_S);
    cudaGetSymbolAddress((void**)&Ph,  g_P);
    cudaGetSymbolAddress((void**)&Zc,  g_Zc);
    cudaGetSymbolAddress((void**)&Dn,  g_Dn);

    cudaFuncSetAttribute(proj_kernel,    cudaFuncAttributeMaxDynamicSharedMemorySize, SMEMSZ);
    cudaFuncSetAttribute(dual_gemm,      cudaFuncAttributeMaxDynamicSharedMemorySize, SMEMSZ);
    cudaFuncSetAttribute(fused79_kernel, cudaFuncAttributeMaxDynamicSharedMemorySize, SMEMSZ);

    // 0) convert all inputs to fp16, one launch
    f2h_all_kernel<<<(N8X + 3*N8W + 255)/256, 256>>>(x, Wq, Wk, Wv, xh, Wh);

    // 1) fused projections: Q, K (+Kt), Vt
    proj_kernel<<<dim3(12,128,1),256,SMEMSZ>>>(xh, Wh, Qh, Kh, Kth, Vth);

    // 2) S chunks + masked P, one launch
    dual_gemm<<<dim3(40,NCHUNK,1),256,SMEMSZ>>>(Vth, Kth, Sh, Qh, Kh, Ph);

    // 3) exclusive prefix of S over chunks (v3: more chains, ring prefetch)
    prefix_kernel<<<1024, 256>>>(Sh);

    // 4) denominator: chunk sums, then fused cumsum-dot
    kchunksum_kernel<<<NCHUNK*BB*DD/256, 256>>>(Kh, Zc);
    zdot_kernel<<<NCHUNK*BB, 1024>>>(Kh, Qh, Zc, Dn);

    // 5) Y = (Q_c·Sprefix^T + P_c·Vt^T) / denom
    fused79_kernel<<<dim3(4,4,NCHUNK),256,SMEMSZ>>>(Qh, Sh, Ph, Vth, Dn, out);
}